// round 3
// baseline (speedup 1.0000x reference)
#include <cuda_runtime.h>

#define BB 512
#define TT 64
#define NI 64
#define HH 128
#define GG 384   // 3*H

// ---------------- scratch (device globals; no allocation allowed) ----------
__device__ float g_WhhT[NI * HH * GG];   // W_hh transposed to [i][k][g]
__device__ float g_hs [BB * NI * HH];
__device__ float g_t1 [BB * NI * HH];
__device__ float g_gc [BB * NI * HH];
__device__ float g_ctx[BB * NI * HH];
__device__ float g_k  [BB * NI * HH];
__device__ float g_v  [BB * NI * HH];

__device__ __forceinline__ float fsig(float x)  { return __fdividef(1.f, 1.f + __expf(-x)); }
__device__ __forceinline__ float ftanh(float x) { return __fdividef(2.f, 1.f + __expf(-2.f * x)) - 1.f; }

// ---------------- K0: transpose W_hh[i][g][k] -> WhhT[i][k][g] -------------
__global__ void whh_transpose_kernel(const float* __restrict__ W_hh) {
    int i = blockIdx.x;
    const float* src = W_hh + i * GG * HH;
    float* dst = g_WhhT + i * GG * HH;
    for (int idx = threadIdx.x; idx < GG * HH; idx += blockDim.x) {
        int g = idx >> 7;        // /128
        int k = idx & 127;
        dst[k * GG + g] = src[idx];
    }
}

// ---------------- K1: GRU scan (persistent h in smem) ----------------------
// grid: (8 batch-tiles, 64 features), block: 256 threads
// thread: j = tid&127 (h index), half = tid>>7 (batch half)
__global__ __launch_bounds__(256) void gru_kernel(
    const float* __restrict__ x,
    const float* __restrict__ W_ih,
    const float* __restrict__ b_ih,
    const float* __restrict__ b_hh)
{
    extern __shared__ float sm[];
    float* hbuf = sm;                 // 2 * 64 * 128
    float* xv   = sm + 2 * 64 * HH;   // 64

    const int i     = blockIdx.y;
    const int btile = blockIdx.x * 64;
    const int j     = threadIdx.x & 127;
    const int half  = threadIdx.x >> 7;

    const float* Wt = g_WhhT + i * HH * GG;

    const float wir = W_ih[i*GG + j],      wiz = W_ih[i*GG + 128 + j],  win = W_ih[i*GG + 256 + j];
    const float bir = b_ih[i*GG + j],      biz = b_ih[i*GG + 128 + j],  bin = b_ih[i*GG + 256 + j];
    const float bhr = b_hh[i*GG + j],      bhz = b_hh[i*GG + 128 + j],  bhn = b_hh[i*GG + 256 + j];

    for (int s = threadIdx.x; s < 64 * HH; s += 256) hbuf[s] = 0.f;
    __syncthreads();

    int cur = 0;
    for (int t = 0; t < TT; ++t) {
        if (threadIdx.x < 64)
            xv[threadIdx.x] = x[(btile + threadIdx.x) * (TT * NI) + t * NI + i];
        __syncthreads();

        float* hc = hbuf + cur * 64 * HH;
        float* hn = hbuf + (cur ^ 1) * 64 * HH;

        for (int c = 0; c < 4; ++c) {
            const int b0 = half * 32 + c * 8;
            float ar[8], az[8], an[8];
            #pragma unroll
            for (int bb = 0; bb < 8; ++bb) { ar[bb] = 0.f; az[bb] = 0.f; an[bb] = 0.f; }

            for (int k4 = 0; k4 < 32; ++k4) {
                float4 hv[8];
                #pragma unroll
                for (int bb = 0; bb < 8; ++bb)
                    hv[bb] = *reinterpret_cast<const float4*>(&hc[(b0 + bb) * HH + k4 * 4]);
                #pragma unroll
                for (int kk = 0; kk < 4; ++kk) {
                    const int k = k4 * 4 + kk;
                    const float wr = Wt[k * GG + j];
                    const float wz = Wt[k * GG + 128 + j];
                    const float wn = Wt[k * GG + 256 + j];
                    #pragma unroll
                    for (int bb = 0; bb < 8; ++bb) {
                        const float h = (kk == 0) ? hv[bb].x : (kk == 1) ? hv[bb].y
                                      : (kk == 2) ? hv[bb].z : hv[bb].w;
                        ar[bb] += h * wr;
                        az[bb] += h * wz;
                        an[bb] += h * wn;
                    }
                }
            }
            #pragma unroll
            for (int bb = 0; bb < 8; ++bb) {
                const int b  = b0 + bb;
                const float xb = xv[b];
                const float r  = fsig(xb * wir + bir + ar[bb] + bhr);
                const float z  = fsig(xb * wiz + biz + az[bb] + bhz);
                const float nn = ftanh(xb * win + bin + r * (an[bb] + bhn));
                const float ho = hc[b * HH + j];
                hn[b * HH + j] = (1.f - z) * nn + z * ho;
            }
        }
        __syncthreads();
        cur ^= 1;
    }

    float* hc = hbuf + cur * 64 * HH;
    for (int bb = 0; bb < 32; ++bb) {
        const int b = half * 32 + bb;
        g_hs[((btile + b) * NI + i) * HH + j] = hc[b * HH + j];
    }
}

// ---------------- LIN: Y[M,128] = act(X[M,128] @ W^T + b) ------------------
// grid: M/16 blocks, block: 128 threads (one per output column)
__global__ __launch_bounds__(128) void lin_kernel(
    const float* __restrict__ X, const float* __restrict__ W,
    const float* __restrict__ bias, float* __restrict__ Y,
    int relu_flag)
{
    extern __shared__ float sm[];
    float* Ws = sm;                  // 128 * 129 (padded)
    float* Xs = sm + 128 * 129;      // 16 * 128
    const int j  = threadIdx.x;
    const int r0 = blockIdx.x * 16;

    for (int idx = j; idx < 128 * 128; idx += 128)
        Ws[(idx >> 7) * 129 + (idx & 127)] = W[idx];
    for (int idx = j; idx < 16 * 128; idx += 128)
        Xs[idx] = X[r0 * 128 + idx];
    __syncthreads();

    const float bj = bias[j];
    const float* wrow = Ws + j * 129;
    #pragma unroll
    for (int rb = 0; rb < 4; ++rb) {
        float a0 = bj, a1 = bj, a2 = bj, a3 = bj;
        #pragma unroll 4
        for (int k = 0; k < 128; ++k) {
            const float w = wrow[k];
            a0 += Xs[(rb * 4 + 0) * 128 + k] * w;
            a1 += Xs[(rb * 4 + 1) * 128 + k] * w;
            a2 += Xs[(rb * 4 + 2) * 128 + k] * w;
            a3 += Xs[(rb * 4 + 3) * 128 + k] * w;
        }
        if (relu_flag) {
            a0 = fmaxf(a0, 0.f); a1 = fmaxf(a1, 0.f);
            a2 = fmaxf(a2, 0.f); a3 = fmaxf(a3, 0.f);
        }
        Y[(r0 + rb * 4 + 0) * 128 + j] = a0;
        Y[(r0 + rb * 4 + 1) * 128 + j] = a1;
        Y[(r0 + rb * 4 + 2) * 128 + j] = a2;
        Y[(r0 + rb * 4 + 3) * 128 + j] = a3;
    }
}

// ---------------- ADJ: Y[b,i,:] = sum_j adj[i,j] * X[b,j,:] ----------------
// grid: (512, 64), block: 128  (adj entries are 0/1 -> plain FMA, no branch)
__global__ __launch_bounds__(128) void adj_kernel(
    const float* __restrict__ adj, const float* __restrict__ Xin,
    float* __restrict__ Y)
{
    __shared__ float arow[64];
    const int b = blockIdx.x, i = blockIdx.y, h = threadIdx.x;
    if (h < 64) arow[h] = adj[i * 64 + h];
    __syncthreads();
    float acc = 0.f;
    const float* xb = Xin + b * 64 * 128;
    #pragma unroll 8
    for (int jj = 0; jj < 64; ++jj)
        acc += arow[jj] * xb[jj * 128 + h];
    Y[(b * 64 + i) * 128 + h] = acc;
}

// ---------------- ATT: q/e/softmax/wctx/out head per batch -----------------
// grid: 512, block: 128
__global__ __launch_bounds__(128) void att_kernel(
    const float* __restrict__ wq_w, const float* __restrict__ wq_b,
    const float* __restrict__ out_w, const float* __restrict__ out_b,
    float* __restrict__ out)
{
    extern __shared__ float sm[];
    float* Wq   = sm;                 // 128 * 129
    float* Wo   = Wq + 128 * 129;     // 128 * 129
    float* xq   = Wo + 128 * 129;     // 128
    float* qs   = xq + 128;           // 128
    float* es   = qs + 128;           // 64
    float* as_  = es + 64;            // 64
    float* wctx = as_ + 64;           // 128

    const int tid = threadIdx.x, b = blockIdx.x;

    for (int idx = tid; idx < 128 * 128; idx += 128) {
        Wq[(idx >> 7) * 129 + (idx & 127)] = wq_w[idx];
        Wo[(idx >> 7) * 129 + (idx & 127)] = out_w[idx];
    }
    xq[tid] = g_ctx[(b * 64 + 63) * 128 + tid];
    __syncthreads();

    {   // q = wq @ ctx[b, -1, :] + bq
        float acc = wq_b[tid];
        const float* wr = Wq + tid * 129;
        #pragma unroll 4
        for (int k = 0; k < 128; ++k) acc += xq[k] * wr[k];
        qs[tid] = acc;
    }
    __syncthreads();

    const int w = tid >> 5, lane = tid & 31;
    const float* kb = g_k + b * 64 * 128;
    const float* vb = g_v + b * 64 * 128;
    for (int i = w; i < 64; i += 4) {     // e[i] = k[b,i,:] . q
        float p = 0.f;
        #pragma unroll
        for (int k = lane; k < 128; k += 32) p += kb[i * 128 + k] * qs[k];
        #pragma unroll
        for (int off = 16; off; off >>= 1) p += __shfl_xor_sync(0xffffffffu, p, off);
        if (lane == 0) es[i] = p;
    }
    __syncthreads();

    if (tid < 32) {                       // softmax over 64 (2 per lane)
        float v0 = es[tid], v1 = es[tid + 32];
        float m = fmaxf(v0, v1);
        #pragma unroll
        for (int off = 16; off; off >>= 1) m = fmaxf(m, __shfl_xor_sync(0xffffffffu, m, off));
        float e0 = __expf(v0 - m), e1 = __expf(v1 - m);
        float s = e0 + e1;
        #pragma unroll
        for (int off = 16; off; off >>= 1) s += __shfl_xor_sync(0xffffffffu, s, off);
        const float inv = __fdividef(1.f, s);
        as_[tid] = e0 * inv; as_[tid + 32] = e1 * inv;
    }
    __syncthreads();

    {   // wctx = sum_i a_i * v[b,i,:]
        float acc = 0.f;
        #pragma unroll 4
        for (int i = 0; i < 64; ++i) acc += as_[i] * vb[i * 128 + tid];
        wctx[tid] = acc;
    }
    __syncthreads();

    {   // out = relu(out0 @ wctx + b0)
        float acc = out_b[tid];
        const float* wr = Wo + tid * 129;
        #pragma unroll 4
        for (int k = 0; k < 128; ++k) acc += wctx[k] * wr[k];
        out[b * 128 + tid] = fmaxf(acc, 0.f);
    }
}

// ---------------- launch ---------------------------------------------------
extern "C" void kernel_launch(void* const* d_in, const int* in_sizes, int n_in,
                              void* d_out, int out_size)
{
    (void)in_sizes; (void)n_in; (void)out_size;
    const float* x    = (const float*)d_in[0];
    const float* W_ih = (const float*)d_in[1];
    const float* W_hh = (const float*)d_in[2];
    const float* b_ih = (const float*)d_in[3];
    const float* b_hh = (const float*)d_in[4];
    const float* fp_w = (const float*)d_in[5];
    const float* fp_b = (const float*)d_in[6];
    const float* g1_w = (const float*)d_in[7];
    const float* g1_b = (const float*)d_in[8];
    const float* g2_w = (const float*)d_in[9];
    const float* g2_b = (const float*)d_in[10];
    const float* wq_w = (const float*)d_in[11];
    const float* wq_b = (const float*)d_in[12];
    const float* wk_w = (const float*)d_in[13];
    const float* wk_b = (const float*)d_in[14];
    const float* wv_w = (const float*)d_in[15];
    const float* wv_b = (const float*)d_in[16];
    const float* o_w  = (const float*)d_in[17];
    const float* o_b  = (const float*)d_in[18];
    const float* adj  = (const float*)d_in[19];

    float* out = (float*)d_out;            // [512,128]
    float* ht  = out + BB * HH;            // [512,64,128] second tuple output

    const int GRU_SMEM = (2 * 64 * HH + 64) * (int)sizeof(float);          // 65792
    const int LIN_SMEM = (128 * 129 + 16 * 128) * (int)sizeof(float);      // 74240
    const int ATT_SMEM = (2 * 128 * 129 + 128 + 128 + 64 + 64 + 128) * (int)sizeof(float); // 134144

    cudaFuncSetAttribute(gru_kernel, cudaFuncAttributeMaxDynamicSharedMemorySize, GRU_SMEM);
    cudaFuncSetAttribute(lin_kernel, cudaFuncAttributeMaxDynamicSharedMemorySize, LIN_SMEM);
    cudaFuncSetAttribute(att_kernel, cudaFuncAttributeMaxDynamicSharedMemorySize, ATT_SMEM);

    float *p_hs, *p_t1, *p_gc, *p_ctx, *p_k, *p_v;
    cudaGetSymbolAddress((void**)&p_hs,  g_hs);
    cudaGetSymbolAddress((void**)&p_t1,  g_t1);
    cudaGetSymbolAddress((void**)&p_gc,  g_gc);
    cudaGetSymbolAddress((void**)&p_ctx, g_ctx);
    cudaGetSymbolAddress((void**)&p_k,   g_k);
    cudaGetSymbolAddress((void**)&p_v,   g_v);

    const int M = BB * NI;                 // 32768 rows for the linears

    whh_transpose_kernel<<<NI, 256>>>(W_hh);
    gru_kernel<<<dim3(8, 64), 256, GRU_SMEM>>>(x, W_ih, b_ih, b_hh);

    lin_kernel<<<M / 16, 128, LIN_SMEM>>>(p_hs, fp_w, fp_b, ht, 0);        // ht (output #2)
    adj_kernel<<<dim3(BB, NI), 128>>>(adj, ht, p_t1);
    lin_kernel<<<M / 16, 128, LIN_SMEM>>>(p_t1, g1_w, g1_b, p_gc, 1);
    adj_kernel<<<dim3(BB, NI), 128>>>(adj, p_gc, p_t1);
    lin_kernel<<<M / 16, 128, LIN_SMEM>>>(p_t1, g2_w, g2_b, p_ctx, 1);
    lin_kernel<<<M / 16, 128, LIN_SMEM>>>(p_ctx, wk_w, wk_b, p_k, 0);
    lin_kernel<<<M / 16, 128, LIN_SMEM>>>(p_ctx, wv_w, wv_b, p_v, 0);
    att_kernel<<<BB, 128, ATT_SMEM>>>(wq_w, wq_b, o_w, o_b, out);
}

// round 8
// speedup vs baseline: 3.1783x; 3.1783x over previous
#include <cuda_runtime.h>
#include <cuda_bf16.h>
#include <cstdint>

#define BB 512
#define TT 64
#define NI 64
#define HH 128
#define GG 384   // 3*H

// ---------------- scratch (device globals; no allocation allowed) ----------
// Fragment-packed W_hh: per feature i: [n0g 16][k 8][plane 2][gate 3][lane 32] u64
__device__ __align__(16) unsigned long long g_Wfrag[(size_t)64 * 16 * 8 * 2 * 3 * 32];
__device__ float g_hs [BB * NI * HH];
__device__ float g_t1 [BB * NI * HH];
__device__ float g_gc [BB * NI * HH];
__device__ float g_ctx[BB * NI * HH];
__device__ float g_k  [BB * NI * HH];
__device__ float g_v  [BB * NI * HH];

__device__ __forceinline__ float fsig(float x)  { return __fdividef(1.f, 1.f + __expf(-x)); }
__device__ __forceinline__ float ftanh(float x) { return __fdividef(2.f, 1.f + __expf(-2.f * x)) - 1.f; }

__device__ __forceinline__ uint16_t f2bf(float f) {
    __nv_bfloat16 b = __float2bfloat16_rn(f);
    return reinterpret_cast<uint16_t&>(b);
}
__device__ __forceinline__ float bf2f(uint16_t u) {
    __nv_bfloat16 b = reinterpret_cast<__nv_bfloat16&>(u);
    return __bfloat162float(b);
}

__device__ __forceinline__ uint32_t smem_to_u32(const void* smem_ptr) {
    uint32_t addr;
    asm("{ .reg .u64 tmp; cvta.to.shared.u64 tmp, %1; cvt.u32.u64 %0, tmp; }"
        : "=r"(addr) : "l"(smem_ptr));
    return addr;
}

// ldmatrix x4: A fragment (m16 x k16 bf16) from swizzled SMEM
#define LDMX4(r, a) \
    asm volatile("ldmatrix.sync.aligned.m8n8.x4.shared.b16 {%0,%1,%2,%3}, [%4];" \
        : "=r"((r)[0]), "=r"((r)[1]), "=r"((r)[2]), "=r"((r)[3]) : "r"(a))

// mma.sync m16n8k16 bf16 -> f32 accumulate
#define MMA16816(c, a, b) \
    asm volatile( \
        "mma.sync.aligned.m16n8k16.row.col.f32.bf16.bf16.f32 " \
        "{%0,%1,%2,%3}, {%4,%5,%6,%7}, {%8,%9}, {%0,%1,%2,%3};" \
        : "+f"((c)[0]), "+f"((c)[1]), "+f"((c)[2]), "+f"((c)[3]) \
        : "r"((a)[0]), "r"((a)[1]), "r"((a)[2]), "r"((a)[3]), \
          "r"((b).x), "r"((b).y))

// ---------------- K0: split W_hh into bf16 hi/lo B-fragment order ----------
// frag idx = ((n0g*8 + k)*2 + plane)*3 + gate ; 32 u64 per frag (one per lane)
// lane L: n = n0g*8 + L/4 ; k0 = kg*16 + (L%4)*2 ; u64 = {pair(k0,k0+1), pair(k0+8,k0+9)}
__global__ void wsplit_kernel(const float* __restrict__ W_hh) {
    const int i = blockIdx.x;
    unsigned long long* dst = g_Wfrag + (size_t)i * 24576;
    const float* W = W_hh + (size_t)i * GG * HH;
    for (int e = threadIdx.x; e < 24576; e += blockDim.x) {
        const int lane = e & 31;
        int e2 = e >> 5;
        const int gate = e2 % 3; e2 /= 3;
        const int plane = e2 & 1; e2 >>= 1;
        const int kg  = e2 & 7;
        const int n0g = e2 >> 3;
        const int n = n0g * 8 + (lane >> 2);
        const int k = kg * 16 + (lane & 3) * 2;
        const float* row = W + (size_t)(gate * 128 + n) * 128;
        const float w0 = row[k],     w1 = row[k + 1];
        const float w2 = row[k + 8], w3 = row[k + 9];
        uint16_t v0, v1, v2, v3;
        if (plane == 0) {
            v0 = f2bf(w0); v1 = f2bf(w1); v2 = f2bf(w2); v3 = f2bf(w3);
        } else {
            v0 = f2bf(w0 - bf2f(f2bf(w0)));
            v1 = f2bf(w1 - bf2f(f2bf(w1)));
            v2 = f2bf(w2 - bf2f(f2bf(w2)));
            v3 = f2bf(w3 - bf2f(f2bf(w3)));
        }
        dst[e] = (unsigned long long)((uint32_t)v0 | ((uint32_t)v1 << 16))
               | ((unsigned long long)((uint32_t)v2 | ((uint32_t)v3 << 16)) << 32);
    }
}

// ---------------- K1: HMMA GRU scan (ping-pong h planes) --------------------
// grid (4 batch-tiles, 64 features), 256 threads = 8 warps.
// Warp w: row-group (w&3)*32 (32 rows), n-half (w>>2) (64 of 128 j-cols).
// SMEM: buf0_hi 32K | buf0_lo 32K | buf1_hi 32K | buf1_lo 32K | x 32K | params
// Step t: READ planes buf[t&1] (h(t-1)), WRITE planes buf[(t+1)&1] (h(t)).
__global__ __launch_bounds__(256, 1) void gru_mma_kernel(
    const float* __restrict__ x,
    const float* __restrict__ W_ih,
    const float* __restrict__ b_ih,
    const float* __restrict__ b_hh)
{
    extern __shared__ __align__(16) unsigned char sm[];
    const uint32_t B0 = smem_to_u32(sm);
    float* xsAll = reinterpret_cast<float*>(sm + 131072);   // [t][r] 64x128
    float* smp   = reinterpret_cast<float*>(sm + 163840);   // 7 x 128 params

    const int tid  = threadIdx.x;
    const int wid  = tid >> 5;
    const int lane = tid & 31;
    const int i      = blockIdx.y;
    const int btile  = blockIdx.x * 128;
    const int rg     = (wid & 3) * 32;      // warp's row group
    const int nh     = wid >> 2;            // warp's n-half (j cols nh*64..+63)

    // zero buf0 (hi+lo = 64KB) — the t=0 read planes
    for (int e = tid; e < 65536 / 16; e += 256)
        reinterpret_cast<uint4*>(sm)[e] = make_uint4(0u, 0u, 0u, 0u);

    if (tid < 128) {          // per-j gate params (bias sums precombined)
        const int j = tid, base = i * GG;
        smp[j]        = W_ih[base + j];
        smp[128 + j]  = W_ih[base + 128 + j];
        smp[256 + j]  = W_ih[base + 256 + j];
        smp[384 + j]  = b_ih[base + j]       + b_hh[base + j];
        smp[512 + j]  = b_ih[base + 128 + j] + b_hh[base + 128 + j];
        smp[640 + j]  = b_ih[base + 256 + j];
        smp[768 + j]  = b_hh[base + 256 + j];
    }

    // preload all x for this CTA: xsAll[t*128 + r]
    for (int e = tid; e < TT * 128; e += 256) {
        const int t = e >> 7, r = e & 127;
        xsAll[e] = x[(size_t)(btile + r) * (TT * NI) + t * NI + i];
    }
    __syncthreads();

    // A-fragment lane geometry (ldmatrix x4: mats = (r0-7,k0),(r8-15,k0),(r0-7,k8),(r8-15,k8))
    const int rA = rg + (lane & 7) + ((lane >> 3) & 1) * 8;
    const uint32_t kcL   = (uint32_t)(lane >> 4);
    const uint32_t row0b = (uint32_t)rA * 256;
    const uint32_t row1b = row0b + 16 * 256;
    const uint32_t swr   = (uint32_t)(rA & 7);

    const unsigned long long* wbase = g_Wfrag + (size_t)i * 24576;

    for (int t = 0; t < TT; ++t) {
        const uint32_t RH = B0 + (uint32_t)(t & 1) * 65536;        // read hi plane
        const uint32_t RL = RH + 32768;                            // read lo plane
        const uint32_t WH = B0 + (uint32_t)((t + 1) & 1) * 65536;  // write hi plane
        const uint32_t WL = WH + 32768;
        const float* xs = xsAll + t * 128;

        #pragma unroll 1
        for (int nc = 0; nc < 4; ++nc) {
            const int nch = nh * 4 + nc;
            // 12 accum frags: (gate 3) x (nf 2) x (mt 2) x 4 vals
            float acc[48];
            #pragma unroll
            for (int q = 0; q < 48; ++q) acc[q] = 0.f;

            #pragma unroll
            for (int k = 0; k < 8; ++k) {
                const uint32_t so = (((uint32_t)(k * 2) + kcL) ^ swr) << 4;
                uint32_t ahi0[4], ahi1[4], alo0[4], alo1[4];
                LDMX4(ahi0, RH + row0b + so);
                LDMX4(ahi1, RH + row1b + so);
                LDMX4(alo0, RL + row0b + so);
                LDMX4(alo1, RL + row1b + so);

                uint2 bh[3][2], bl[3][2];
                #pragma unroll
                for (int nf = 0; nf < 2; ++nf) {
                    const int n0g = nch * 2 + nf;
                    const unsigned long long* fb =
                        wbase + (size_t)((n0g * 8 + k) * 2) * 3 * 32 + lane;
                    #pragma unroll
                    for (int g = 0; g < 3; ++g) {
                        bh[g][nf] = *reinterpret_cast<const uint2*>(fb + (size_t)g * 32);
                        bl[g][nf] = *reinterpret_cast<const uint2*>(fb + (size_t)(3 + g) * 32);
                    }
                }

                #pragma unroll
                for (int g = 0; g < 3; ++g) {
                    #pragma unroll
                    for (int nf = 0; nf < 2; ++nf) {
                        float* c0 = &acc[((g * 2 + nf) * 2 + 0) * 4];
                        float* c1 = &acc[((g * 2 + nf) * 2 + 1) * 4];
                        MMA16816(c0, ahi0, bh[g][nf]);
                        MMA16816(c0, ahi0, bl[g][nf]);
                        MMA16816(c0, alo0, bh[g][nf]);
                        MMA16816(c1, ahi1, bh[g][nf]);
                        MMA16816(c1, ahi1, bl[g][nf]);
                        MMA16816(c1, alo1, bh[g][nf]);
                    }
                }
            }

            // ---- epilogue for this nchunk (j columns nch*16 .. +15) ----
            #pragma unroll
            for (int nf = 0; nf < 2; ++nf) {
                const int j0 = nch * 16 + nf * 8 + (lane & 3) * 2;
                const float2 wir = *reinterpret_cast<const float2*>(&smp[j0]);
                const float2 wiz = *reinterpret_cast<const float2*>(&smp[128 + j0]);
                const float2 win = *reinterpret_cast<const float2*>(&smp[256 + j0]);
                const float2 brr = *reinterpret_cast<const float2*>(&smp[384 + j0]);
                const float2 bzz = *reinterpret_cast<const float2*>(&smp[512 + j0]);
                const float2 bin = *reinterpret_cast<const float2*>(&smp[640 + j0]);
                const float2 bhn = *reinterpret_cast<const float2*>(&smp[768 + j0]);
                const uint32_t colsw = (uint32_t)(j0 >> 3);
                const uint32_t colb  = (uint32_t)(j0 & 7) * 2;

                #pragma unroll
                for (int mt = 0; mt < 2; ++mt) {
                    #pragma unroll
                    for (int half = 0; half < 2; ++half) {
                        const int r = rg + mt * 16 + (lane >> 2) + half * 8;
                        const uint32_t ha = (uint32_t)r * 256 +
                            ((colsw ^ (uint32_t)(r & 7)) << 4) + colb;
                        uint32_t ohi, olo;
                        asm volatile("ld.shared.b32 %0, [%1];" : "=r"(ohi) : "r"(RH + ha));
                        asm volatile("ld.shared.b32 %0, [%1];" : "=r"(olo) : "r"(RL + ha));
                        const float ho0 = __uint_as_float(ohi << 16) +
                                          __uint_as_float(olo << 16);
                        const float ho1 = __uint_as_float(ohi & 0xffff0000u) +
                                          __uint_as_float(olo & 0xffff0000u);
                        const float xb = xs[r];

                        const float* aR = &acc[((0 * 2 + nf) * 2 + mt) * 4 + half * 2];
                        const float* aZ = &acc[((1 * 2 + nf) * 2 + mt) * 4 + half * 2];
                        const float* aN = &acc[((2 * 2 + nf) * 2 + mt) * 4 + half * 2];

                        const float r0 = fsig(aR[0] + xb * wir.x + brr.x);
                        const float z0 = fsig(aZ[0] + xb * wiz.x + bzz.x);
                        const float n0 = ftanh(xb * win.x + bin.x + r0 * (aN[0] + bhn.x));
                        const float h0 = (1.f - z0) * n0 + z0 * ho0;

                        const float r1 = fsig(aR[1] + xb * wir.y + brr.y);
                        const float z1 = fsig(aZ[1] + xb * wiz.y + bzz.y);
                        const float n1 = ftanh(xb * win.y + bin.y + r1 * (aN[1] + bhn.y));
                        const float h1 = (1.f - z1) * n1 + z1 * ho1;

                        uint32_t phi;
                        asm("cvt.rn.bf16x2.f32 %0, %1, %2;" : "=r"(phi) : "f"(h1), "f"(h0));
                        const float e0 = h0 - __uint_as_float(phi << 16);
                        const float e1 = h1 - __uint_as_float(phi & 0xffff0000u);
                        uint32_t plo;
                        asm("cvt.rn.bf16x2.f32 %0, %1, %2;" : "=r"(plo) : "f"(e1), "f"(e0));
                        asm volatile("st.shared.b32 [%0], %1;" :: "r"(WH + ha), "r"(phi) : "memory");
                        asm volatile("st.shared.b32 [%0], %1;" :: "r"(WL + ha), "r"(plo) : "memory");
                    }
                }
            }
        }
        __syncthreads();   // h(t) fully written before step t+1 reads it
    }

    // final h is in buf[(TT)&1] = buf0 (TT even): planes at B0 / B0+32768
    for (int e = tid; e < 128 * 128; e += 256) {
        const int r = e >> 7, j = e & 127;
        const uint32_t ha = (uint32_t)r * 256 +
            ((((uint32_t)(j >> 3)) ^ (uint32_t)(r & 7)) << 4) + (uint32_t)(j & 7) * 2;
        uint16_t hv, lv;
        asm volatile("ld.shared.u16 %0, [%1];" : "=h"(hv) : "r"(B0 + ha));
        asm volatile("ld.shared.u16 %0, [%1];" : "=h"(lv) : "r"(B0 + 32768 + ha));
        g_hs[((size_t)(btile + r) * NI + i) * HH + j] = bf2f(hv) + bf2f(lv);
    }
}

// ---------------- LIN: Y[M,128] = act(X[M,128] @ W^T + b) ------------------
__global__ __launch_bounds__(128) void lin_kernel(
    const float* __restrict__ X, const float* __restrict__ W,
    const float* __restrict__ bias, float* __restrict__ Y,
    int relu_flag)
{
    extern __shared__ float smf[];
    float* Ws = smf;                 // 128 * 129 (padded)
    float* Xs = smf + 128 * 129;     // 16 * 128
    const int j  = threadIdx.x;
    const int r0 = blockIdx.x * 16;

    for (int idx = j; idx < 128 * 128; idx += 128)
        Ws[(idx >> 7) * 129 + (idx & 127)] = W[idx];
    for (int idx = j; idx < 16 * 128; idx += 128)
        Xs[idx] = X[r0 * 128 + idx];
    __syncthreads();

    const float bj = bias[j];
    const float* wrow = Ws + j * 129;
    #pragma unroll
    for (int rb = 0; rb < 4; ++rb) {
        float a0 = bj, a1 = bj, a2 = bj, a3 = bj;
        #pragma unroll 4
        for (int k = 0; k < 128; ++k) {
            const float w = wrow[k];
            a0 += Xs[(rb * 4 + 0) * 128 + k] * w;
            a1 += Xs[(rb * 4 + 1) * 128 + k] * w;
            a2 += Xs[(rb * 4 + 2) * 128 + k] * w;
            a3 += Xs[(rb * 4 + 3) * 128 + k] * w;
        }
        if (relu_flag) {
            a0 = fmaxf(a0, 0.f); a1 = fmaxf(a1, 0.f);
            a2 = fmaxf(a2, 0.f); a3 = fmaxf(a3, 0.f);
        }
        Y[(r0 + rb * 4 + 0) * 128 + j] = a0;
        Y[(r0 + rb * 4 + 1) * 128 + j] = a1;
        Y[(r0 + rb * 4 + 2) * 128 + j] = a2;
        Y[(r0 + rb * 4 + 3) * 128 + j] = a3;
    }
}

// ---------------- ADJ: Y[b,i,:] = sum_j adj[i,j] * X[b,j,:] ----------------
__global__ __launch_bounds__(128) void adj_kernel(
    const float* __restrict__ adj, const float* __restrict__ Xin,
    float* __restrict__ Y)
{
    __shared__ float arow[64];
    const int b = blockIdx.x, i = blockIdx.y, h = threadIdx.x;
    if (h < 64) arow[h] = adj[i * 64 + h];
    __syncthreads();
    float acc = 0.f;
    const float* xb = Xin + b * 64 * 128;
    #pragma unroll 8
    for (int jj = 0; jj < 64; ++jj)
        acc += arow[jj] * xb[jj * 128 + h];
    Y[(b * 64 + i) * 128 + h] = acc;
}

// ---------------- ATT: q/e/softmax/wctx/out head per batch -----------------
__global__ __launch_bounds__(128) void att_kernel(
    const float* __restrict__ wq_w, const float* __restrict__ wq_b,
    const float* __restrict__ out_w, const float* __restrict__ out_b,
    float* __restrict__ out)
{
    extern __shared__ float smf[];
    float* Wq   = smf;                // 128 * 129
    float* Wo   = Wq + 128 * 129;     // 128 * 129
    float* xq   = Wo + 128 * 129;     // 128
    float* qs   = xq + 128;           // 128
    float* es   = qs + 128;           // 64
    float* as_  = es + 64;            // 64
    float* wctx = as_ + 64;           // 128

    const int tid = threadIdx.x, b = blockIdx.x;

    for (int idx = tid; idx < 128 * 128; idx += 128) {
        Wq[(idx >> 7) * 129 + (idx & 127)] = wq_w[idx];
        Wo[(idx >> 7) * 129 + (idx & 127)] = out_w[idx];
    }
    xq[tid] = g_ctx[(b * 64 + 63) * 128 + tid];
    __syncthreads();

    {   // q = wq @ ctx[b, -1, :] + bq
        float acc = wq_b[tid];
        const float* wr = Wq + tid * 129;
        #pragma unroll 4
        for (int k = 0; k < 128; ++k) acc += xq[k] * wr[k];
        qs[tid] = acc;
    }
    __syncthreads();

    const int w = tid >> 5, lane = tid & 31;
    const float* kb = g_k + b * 64 * 128;
    const float* vb = g_v + b * 64 * 128;
    for (int i = w; i < 64; i += 4) {     // e[i] = k[b,i,:] . q
        float p = 0.f;
        #pragma unroll
        for (int k = lane; k < 128; k += 32) p += kb[i * 128 + k] * qs[k];
        #pragma unroll
        for (int off = 16; off; off >>= 1) p += __shfl_xor_sync(0xffffffffu, p, off);
        if (lane == 0) es[i] = p;
    }
    __syncthreads();

    if (tid < 32) {                       // softmax over 64 (2 per lane)
        float v0 = es[tid], v1 = es[tid + 32];
        float m = fmaxf(v0, v1);
        #pragma unroll
        for (int off = 16; off; off >>= 1) m = fmaxf(m, __shfl_xor_sync(0xffffffffu, m, off));
        float e0 = __expf(v0 - m), e1 = __expf(v1 - m);
        float s = e0 + e1;
        #pragma unroll
        for (int off = 16; off; off >>= 1) s += __shfl_xor_sync(0xffffffffu, s, off);
        const float inv = __fdividef(1.f, s);
        as_[tid] = e0 * inv; as_[tid + 32] = e1 * inv;
    }
    __syncthreads();

    {   // wctx = sum_i a_i * v[b,i,:]
        float acc = 0.f;
        #pragma unroll 4
        for (int i = 0; i < 64; ++i) acc += as_[i] * vb[i * 128 + tid];
        wctx[tid] = acc;
    }
    __syncthreads();

    {   // out = relu(out0 @ wctx + b0)
        float acc = out_b[tid];
        const float* wr = Wo + tid * 129;
        #pragma unroll 4
        for (int k = 0; k < 128; ++k) acc += wctx[k] * wr[k];
        out[b * 128 + tid] = fmaxf(acc, 0.f);
    }
}

// ---------------- launch ---------------------------------------------------
extern "C" void kernel_launch(void* const* d_in, const int* in_sizes, int n_in,
                              void* d_out, int out_size)
{
    (void)in_sizes; (void)n_in; (void)out_size;
    const float* x    = (const float*)d_in[0];
    const float* W_ih = (const float*)d_in[1];
    const float* W_hh = (const float*)d_in[2];
    const float* b_ih = (const float*)d_in[3];
    const float* b_hh = (const float*)d_in[4];
    const float* fp_w = (const float*)d_in[5];
    const float* fp_b = (const float*)d_in[6];
    const float* g1_w = (const float*)d_in[7];
    const float* g1_b = (const float*)d_in[8];
    const float* g2_w = (const float*)d_in[9];
    const float* g2_b = (const float*)d_in[10];
    const float* wq_w = (const float*)d_in[11];
    const float* wq_b = (const float*)d_in[12];
    const float* wk_w = (const float*)d_in[13];
    const float* wk_b = (const float*)d_in[14];
    const float* wv_w = (const float*)d_in[15];
    const float* wv_b = (const float*)d_in[16];
    const float* o_w  = (const float*)d_in[17];
    const float* o_b  = (const float*)d_in[18];
    const float* adj  = (const float*)d_in[19];

    float* out = (float*)d_out;            // [512,128]
    float* ht  = out + BB * HH;            // [512,64,128] second tuple output

    const int GRU_SMEM = 131072 + 32768 + 3584;                            // 167424
    const int LIN_SMEM = (128 * 129 + 16 * 128) * (int)sizeof(float);      // 74240
    const int ATT_SMEM = (2 * 128 * 129 + 128 + 128 + 64 + 64 + 128) * (int)sizeof(float); // 134144

    cudaFuncSetAttribute(gru_mma_kernel, cudaFuncAttributeMaxDynamicSharedMemorySize, GRU_SMEM);
    cudaFuncSetAttribute(lin_kernel, cudaFuncAttributeMaxDynamicSharedMemorySize, LIN_SMEM);
    cudaFuncSetAttribute(att_kernel, cudaFuncAttributeMaxDynamicSharedMemorySize, ATT_SMEM);

    float *p_hs, *p_t1, *p_gc, *p_ctx, *p_k, *p_v;
    cudaGetSymbolAddress((void**)&p_hs,  g_hs);
    cudaGetSymbolAddress((void**)&p_t1,  g_t1);
    cudaGetSymbolAddress((void**)&p_gc,  g_gc);
    cudaGetSymbolAddress((void**)&p_ctx, g_ctx);
    cudaGetSymbolAddress((void**)&p_k,   g_k);
    cudaGetSymbolAddress((void**)&p_v,   g_v);

    const int M = BB * NI;                 // 32768 rows for the linears

    wsplit_kernel<<<NI, 256>>>(W_hh);
    gru_mma_kernel<<<dim3(4, 64), 256, GRU_SMEM>>>(x, W_ih, b_ih, b_hh);

    lin_kernel<<<M / 16, 128, LIN_SMEM>>>(p_hs, fp_w, fp_b, ht, 0);        // ht (output #2)
    adj_kernel<<<dim3(BB, NI), 128>>>(adj, ht, p_t1);
    lin_kernel<<<M / 16, 128, LIN_SMEM>>>(p_t1, g1_w, g1_b, p_gc, 1);
    adj_kernel<<<dim3(BB, NI), 128>>>(adj, p_gc, p_t1);
    lin_kernel<<<M / 16, 128, LIN_SMEM>>>(p_t1, g2_w, g2_b, p_ctx, 1);
    lin_kernel<<<M / 16, 128, LIN_SMEM>>>(p_ctx, wk_w, wk_b, p_k, 0);
    lin_kernel<<<M / 16, 128, LIN_SMEM>>>(p_ctx, wv_w, wv_b, p_v, 0);
    att_kernel<<<BB, 128, ATT_SMEM>>>(wq_w, wq_b, o_w, o_b, out);
}

// round 9
// speedup vs baseline: 3.3819x; 1.0641x over previous
#include <cuda_runtime.h>
#include <cuda_bf16.h>
#include <cstdint>

#define BB 512
#define TT 64
#define NI 64
#define HH 128
#define GG 384   // 3*H

// ---------------- scratch (device globals; no allocation allowed) ----------
// Fragment-packed W_hh: per feature i: [n0g 16][k 8][plane 2][gate 3][lane 32] u64
__device__ __align__(16) unsigned long long g_Wfrag[(size_t)64 * 16 * 8 * 2 * 3 * 32];
__device__ float g_hs [BB * NI * HH];
__device__ float g_t1 [BB * NI * HH];
__device__ float g_gc [BB * NI * HH];
__device__ float g_ctx[BB * NI * HH];
__device__ float g_k  [BB * NI * HH];
__device__ float g_v  [BB * NI * HH];

__device__ __forceinline__ float fsig(float x)  { return __fdividef(1.f, 1.f + __expf(-x)); }
__device__ __forceinline__ float ftanh(float x) { return __fdividef(2.f, 1.f + __expf(-2.f * x)) - 1.f; }

__device__ __forceinline__ uint16_t f2bf(float f) {
    __nv_bfloat16 b = __float2bfloat16_rn(f);
    return reinterpret_cast<uint16_t&>(b);
}
__device__ __forceinline__ float bf2f(uint16_t u) {
    __nv_bfloat16 b = reinterpret_cast<__nv_bfloat16&>(u);
    return __bfloat162float(b);
}

__device__ __forceinline__ uint32_t smem_to_u32(const void* smem_ptr) {
    uint32_t addr;
    asm("{ .reg .u64 tmp; cvta.to.shared.u64 tmp, %1; cvt.u32.u64 %0, tmp; }"
        : "=r"(addr) : "l"(smem_ptr));
    return addr;
}

// ldmatrix x4: A fragment (m16 x k16 bf16) from swizzled SMEM
#define LDMX4(r, a) \
    asm volatile("ldmatrix.sync.aligned.m8n8.x4.shared.b16 {%0,%1,%2,%3}, [%4];" \
        : "=r"((r)[0]), "=r"((r)[1]), "=r"((r)[2]), "=r"((r)[3]) : "r"(a))

// mma.sync m16n8k16 bf16 -> f32 accumulate
#define MMA16816(c, a, b) \
    asm volatile( \
        "mma.sync.aligned.m16n8k16.row.col.f32.bf16.bf16.f32 " \
        "{%0,%1,%2,%3}, {%4,%5,%6,%7}, {%8,%9}, {%0,%1,%2,%3};" \
        : "+f"((c)[0]), "+f"((c)[1]), "+f"((c)[2]), "+f"((c)[3]) \
        : "r"((a)[0]), "r"((a)[1]), "r"((a)[2]), "r"((a)[3]), \
          "r"((b).x), "r"((b).y))

// ---------------- K0: split W_hh into bf16 hi/lo B-fragment order ----------
// frag idx = ((n0g*8 + k)*2 + plane)*3 + gate ; 32 u64 per frag (one per lane)
// lane L: n = n0g*8 + L/4 ; k0 = kg*16 + (L%4)*2 ; u64 = {pair(k0,k0+1), pair(k0+8,k0+9)}
__global__ void wsplit_kernel(const float* __restrict__ W_hh) {
    const int i = blockIdx.x;
    unsigned long long* dst = g_Wfrag + (size_t)i * 24576;
    const float* W = W_hh + (size_t)i * GG * HH;
    for (int e = threadIdx.x; e < 24576; e += blockDim.x) {
        const int lane = e & 31;
        int e2 = e >> 5;
        const int gate = e2 % 3; e2 /= 3;
        const int plane = e2 & 1; e2 >>= 1;
        const int kg  = e2 & 7;
        const int n0g = e2 >> 3;
        const int n = n0g * 8 + (lane >> 2);
        const int k = kg * 16 + (lane & 3) * 2;
        const float* row = W + (size_t)(gate * 128 + n) * 128;
        const float w0 = row[k],     w1 = row[k + 1];
        const float w2 = row[k + 8], w3 = row[k + 9];
        uint16_t v0, v1, v2, v3;
        if (plane == 0) {
            v0 = f2bf(w0); v1 = f2bf(w1); v2 = f2bf(w2); v3 = f2bf(w3);
        } else {
            v0 = f2bf(w0 - bf2f(f2bf(w0)));
            v1 = f2bf(w1 - bf2f(f2bf(w1)));
            v2 = f2bf(w2 - bf2f(f2bf(w2)));
            v3 = f2bf(w3 - bf2f(f2bf(w3)));
        }
        dst[e] = (unsigned long long)((uint32_t)v0 | ((uint32_t)v1 << 16))
               | ((unsigned long long)((uint32_t)v2 | ((uint32_t)v3 << 16)) << 32);
    }
}

// ---------------- K1: HMMA GRU scan (ping-pong, 2rg x 4nh warp map) --------
// grid (4 batch-tiles, 64 features), 256 threads = 8 warps.
// Warp w: row-group (w&1)*64 (64 rows via 4 m-tiles), n-quarter (w>>1) (32 j-cols).
// Only 2 warps share each n-quarter -> 2x (not 4x) redundant W-fragment loads.
// SMEM: buf0_hi 32K | buf0_lo 32K | buf1_hi 32K | buf1_lo 32K | x 32K | params
// Step t: READ planes buf[t&1] (h(t-1)), WRITE planes buf[(t+1)&1] (h(t)).
__global__ __launch_bounds__(256, 1) void gru_mma_kernel(
    const float* __restrict__ x,
    const float* __restrict__ W_ih,
    const float* __restrict__ b_ih,
    const float* __restrict__ b_hh)
{
    extern __shared__ __align__(16) unsigned char sm[];
    const uint32_t B0 = smem_to_u32(sm);
    float* xsAll = reinterpret_cast<float*>(sm + 131072);   // [t][r] 64x128
    float* smp   = reinterpret_cast<float*>(sm + 163840);   // 7 x 128 params

    const int tid  = threadIdx.x;
    const int wid  = tid >> 5;
    const int lane = tid & 31;
    const int i      = blockIdx.y;
    const int btile  = blockIdx.x * 128;
    const int rg     = (wid & 1) * 64;      // warp's row group (64 rows)
    const int nh     = wid >> 1;            // warp's n-quarter (j cols nh*32..+31)

    // zero buf0 (hi+lo = 64KB) — the t=0 read planes
    for (int e = tid; e < 65536 / 16; e += 256)
        reinterpret_cast<uint4*>(sm)[e] = make_uint4(0u, 0u, 0u, 0u);

    if (tid < 128) {          // per-j gate params (bias sums precombined)
        const int j = tid, base = i * GG;
        smp[j]        = W_ih[base + j];
        smp[128 + j]  = W_ih[base + 128 + j];
        smp[256 + j]  = W_ih[base + 256 + j];
        smp[384 + j]  = b_ih[base + j]       + b_hh[base + j];
        smp[512 + j]  = b_ih[base + 128 + j] + b_hh[base + 128 + j];
        smp[640 + j]  = b_ih[base + 256 + j];
        smp[768 + j]  = b_hh[base + 256 + j];
    }

    // preload all x for this CTA: xsAll[t*128 + r]
    for (int e = tid; e < TT * 128; e += 256) {
        const int t = e >> 7, r = e & 127;
        xsAll[e] = x[(size_t)(btile + r) * (TT * NI) + t * NI + i];
    }
    __syncthreads();

    // A-fragment lane geometry (ldmatrix x4: mats = (r0-7,k0),(r8-15,k0),(r0-7,k8),(r8-15,k8))
    const int rA = rg + (lane & 7) + ((lane >> 3) & 1) * 8;
    const uint32_t kcL = (uint32_t)(lane >> 4);
    uint32_t rowb[4];
    #pragma unroll
    for (int mt = 0; mt < 4; ++mt) rowb[mt] = (uint32_t)(rA + mt * 16) * 256;
    const uint32_t swr = (uint32_t)(rA & 7);

    const unsigned long long* wbase = g_Wfrag + (size_t)i * 24576;

    for (int t = 0; t < TT; ++t) {
        const uint32_t RH = B0 + (uint32_t)(t & 1) * 65536;        // read hi plane
        const uint32_t RL = RH + 32768;                            // read lo plane
        const uint32_t WH = B0 + (uint32_t)((t + 1) & 1) * 65536;  // write hi plane
        const uint32_t WL = WH + 32768;
        const float* xs = xsAll + t * 128;

        #pragma unroll 1
        for (int nc = 0; nc < 2; ++nc) {
            const int nch = nh * 2 + nc;
            // 24 accum frags: (gate 3) x (nf 2) x (mt 4) x 4 vals
            float acc[96];
            #pragma unroll
            for (int q = 0; q < 96; ++q) acc[q] = 0.f;

            #pragma unroll
            for (int k = 0; k < 8; ++k) {
                // B fragments first (gmem/L2 — issue early)
                uint2 bh[3][2], bl[3][2];
                #pragma unroll
                for (int nf = 0; nf < 2; ++nf) {
                    const int n0g = nch * 2 + nf;
                    const unsigned long long* fb =
                        wbase + (size_t)((n0g * 8 + k) * 2) * 3 * 32 + lane;
                    #pragma unroll
                    for (int g = 0; g < 3; ++g) {
                        bh[g][nf] = *reinterpret_cast<const uint2*>(fb + (size_t)g * 32);
                        bl[g][nf] = *reinterpret_cast<const uint2*>(fb + (size_t)(3 + g) * 32);
                    }
                }

                const uint32_t so = (((uint32_t)(k * 2) + kcL) ^ swr) << 4;
                uint32_t ahi[4][4], alo[4][4];
                #pragma unroll
                for (int mt = 0; mt < 4; ++mt) {
                    LDMX4(ahi[mt], RH + rowb[mt] + so);
                    LDMX4(alo[mt], RL + rowb[mt] + so);
                }

                #pragma unroll
                for (int g = 0; g < 3; ++g) {
                    #pragma unroll
                    for (int nf = 0; nf < 2; ++nf) {
                        #pragma unroll
                        for (int mt = 0; mt < 4; ++mt) {
                            float* c = &acc[((g * 2 + nf) * 4 + mt) * 4];
                            MMA16816(c, ahi[mt], bh[g][nf]);
                            MMA16816(c, ahi[mt], bl[g][nf]);
                            MMA16816(c, alo[mt], bh[g][nf]);
                        }
                    }
                }
            }

            // ---- epilogue for this nchunk (j columns nch*16 .. +15) ----
            #pragma unroll
            for (int nf = 0; nf < 2; ++nf) {
                const int j0 = nch * 16 + nf * 8 + (lane & 3) * 2;
                const float2 wir = *reinterpret_cast<const float2*>(&smp[j0]);
                const float2 wiz = *reinterpret_cast<const float2*>(&smp[128 + j0]);
                const float2 win = *reinterpret_cast<const float2*>(&smp[256 + j0]);
                const float2 brr = *reinterpret_cast<const float2*>(&smp[384 + j0]);
                const float2 bzz = *reinterpret_cast<const float2*>(&smp[512 + j0]);
                const float2 bin = *reinterpret_cast<const float2*>(&smp[640 + j0]);
                const float2 bhn = *reinterpret_cast<const float2*>(&smp[768 + j0]);
                const uint32_t colsw = (uint32_t)(j0 >> 3);
                const uint32_t colb  = (uint32_t)(j0 & 7) * 2;

                #pragma unroll
                for (int mt = 0; mt < 4; ++mt) {
                    #pragma unroll
                    for (int half = 0; half < 2; ++half) {
                        const int r = rg + mt * 16 + (lane >> 2) + half * 8;
                        const uint32_t ha = (uint32_t)r * 256 +
                            ((colsw ^ (uint32_t)(r & 7)) << 4) + colb;
                        uint32_t ohi, olo;
                        asm volatile("ld.shared.b32 %0, [%1];" : "=r"(ohi) : "r"(RH + ha));
                        asm volatile("ld.shared.b32 %0, [%1];" : "=r"(olo) : "r"(RL + ha));
                        const float ho0 = __uint_as_float(ohi << 16) +
                                          __uint_as_float(olo << 16);
                        const float ho1 = __uint_as_float(ohi & 0xffff0000u) +
                                          __uint_as_float(olo & 0xffff0000u);
                        const float xb = xs[r];

                        const float* aR = &acc[((0 * 2 + nf) * 4 + mt) * 4 + half * 2];
                        const float* aZ = &acc[((1 * 2 + nf) * 4 + mt) * 4 + half * 2];
                        const float* aN = &acc[((2 * 2 + nf) * 4 + mt) * 4 + half * 2];

                        const float r0 = fsig(aR[0] + xb * wir.x + brr.x);
                        const float z0 = fsig(aZ[0] + xb * wiz.x + bzz.x);
                        const float n0 = ftanh(xb * win.x + bin.x + r0 * (aN[0] + bhn.x));
                        const float h0 = (1.f - z0) * n0 + z0 * ho0;

                        const float r1 = fsig(aR[1] + xb * wir.y + brr.y);
                        const float z1 = fsig(aZ[1] + xb * wiz.y + bzz.y);
                        const float n1 = ftanh(xb * win.y + bin.y + r1 * (aN[1] + bhn.y));
                        const float h1 = (1.f - z1) * n1 + z1 * ho1;

                        uint32_t phi;
                        asm("cvt.rn.bf16x2.f32 %0, %1, %2;" : "=r"(phi) : "f"(h1), "f"(h0));
                        const float e0 = h0 - __uint_as_float(phi << 16);
                        const float e1 = h1 - __uint_as_float(phi & 0xffff0000u);
                        uint32_t plo;
                        asm("cvt.rn.bf16x2.f32 %0, %1, %2;" : "=r"(plo) : "f"(e1), "f"(e0));
                        asm volatile("st.shared.b32 [%0], %1;" :: "r"(WH + ha), "r"(phi) : "memory");
                        asm volatile("st.shared.b32 [%0], %1;" :: "r"(WL + ha), "r"(plo) : "memory");
                    }
                }
            }
        }
        __syncthreads();   // h(t) fully written before step t+1 reads it
    }

    // final h is in buf[(TT)&1] = buf0 (TT even): planes at B0 / B0+32768
    for (int e = tid; e < 128 * 128; e += 256) {
        const int r = e >> 7, j = e & 127;
        const uint32_t ha = (uint32_t)r * 256 +
            ((((uint32_t)(j >> 3)) ^ (uint32_t)(r & 7)) << 4) + (uint32_t)(j & 7) * 2;
        uint16_t hv, lv;
        asm volatile("ld.shared.u16 %0, [%1];" : "=h"(hv) : "r"(B0 + ha));
        asm volatile("ld.shared.u16 %0, [%1];" : "=h"(lv) : "r"(B0 + 32768 + ha));
        g_hs[((size_t)(btile + r) * NI + i) * HH + j] = bf2f(hv) + bf2f(lv);
    }
}

// ---------------- LIN: Y[M,128] = act(X[M,128] @ W^T + b) ------------------
__global__ __launch_bounds__(128) void lin_kernel(
    const float* __restrict__ X, const float* __restrict__ W,
    const float* __restrict__ bias, float* __restrict__ Y,
    int relu_flag)
{
    extern __shared__ float smf[];
    float* Ws = smf;                 // 128 * 129 (padded)
    float* Xs = smf + 128 * 129;     // 16 * 128
    const int j  = threadIdx.x;
    const int r0 = blockIdx.x * 16;

    for (int idx = j; idx < 128 * 128; idx += 128)
        Ws[(idx >> 7) * 129 + (idx & 127)] = W[idx];
    for (int idx = j; idx < 16 * 128; idx += 128)
        Xs[idx] = X[r0 * 128 + idx];
    __syncthreads();

    const float bj = bias[j];
    const float* wrow = Ws + j * 129;
    #pragma unroll
    for (int rb = 0; rb < 4; ++rb) {
        float a0 = bj, a1 = bj, a2 = bj, a3 = bj;
        #pragma unroll 4
        for (int k = 0; k < 128; ++k) {
            const float w = wrow[k];
            a0 += Xs[(rb * 4 + 0) * 128 + k] * w;
            a1 += Xs[(rb * 4 + 1) * 128 + k] * w;
            a2 += Xs[(rb * 4 + 2) * 128 + k] * w;
            a3 += Xs[(rb * 4 + 3) * 128 + k] * w;
        }
        if (relu_flag) {
            a0 = fmaxf(a0, 0.f); a1 = fmaxf(a1, 0.f);
            a2 = fmaxf(a2, 0.f); a3 = fmaxf(a3, 0.f);
        }
        Y[(r0 + rb * 4 + 0) * 128 + j] = a0;
        Y[(r0 + rb * 4 + 1) * 128 + j] = a1;
        Y[(r0 + rb * 4 + 2) * 128 + j] = a2;
        Y[(r0 + rb * 4 + 3) * 128 + j] = a3;
    }
}

// ---------------- ADJ: Y[b,i,:] = sum_j adj[i,j] * X[b,j,:] ----------------
__global__ __launch_bounds__(128) void adj_kernel(
    const float* __restrict__ adj, const float* __restrict__ Xin,
    float* __restrict__ Y)
{
    __shared__ float arow[64];
    const int b = blockIdx.x, i = blockIdx.y, h = threadIdx.x;
    if (h < 64) arow[h] = adj[i * 64 + h];
    __syncthreads();
    float acc = 0.f;
    const float* xb = Xin + b * 64 * 128;
    #pragma unroll 8
    for (int jj = 0; jj < 64; ++jj)
        acc += arow[jj] * xb[jj * 128 + h];
    Y[(b * 64 + i) * 128 + h] = acc;
}

// ---------------- ATT: q/e/softmax/wctx/out head per batch -----------------
__global__ __launch_bounds__(128) void att_kernel(
    const float* __restrict__ wq_w, const float* __restrict__ wq_b,
    const float* __restrict__ out_w, const float* __restrict__ out_b,
    float* __restrict__ out)
{
    extern __shared__ float smf[];
    float* Wq   = smf;                // 128 * 129
    float* Wo   = Wq + 128 * 129;     // 128 * 129
    float* xq   = Wo + 128 * 129;     // 128
    float* qs   = xq + 128;           // 128
    float* es   = qs + 128;           // 64
    float* as_  = es + 64;            // 64
    float* wctx = as_ + 64;           // 128

    const int tid = threadIdx.x, b = blockIdx.x;

    for (int idx = tid; idx < 128 * 128; idx += 128) {
        Wq[(idx >> 7) * 129 + (idx & 127)] = wq_w[idx];
        Wo[(idx >> 7) * 129 + (idx & 127)] = out_w[idx];
    }
    xq[tid] = g_ctx[(b * 64 + 63) * 128 + tid];
    __syncthreads();

    {   // q = wq @ ctx[b, -1, :] + bq
        float acc = wq_b[tid];
        const float* wr = Wq + tid * 129;
        #pragma unroll 4
        for (int k = 0; k < 128; ++k) acc += xq[k] * wr[k];
        qs[tid] = acc;
    }
    __syncthreads();

    const int w = tid >> 5, lane = tid & 31;
    const float* kb = g_k + b * 64 * 128;
    const float* vb = g_v + b * 64 * 128;
    for (int i = w; i < 64; i += 4) {     // e[i] = k[b,i,:] . q
        float p = 0.f;
        #pragma unroll
        for (int k = lane; k < 128; k += 32) p += kb[i * 128 + k] * qs[k];
        #pragma unroll
        for (int off = 16; off; off >>= 1) p += __shfl_xor_sync(0xffffffffu, p, off);
        if (lane == 0) es[i] = p;
    }
    __syncthreads();

    if (tid < 32) {                       // softmax over 64 (2 per lane)
        float v0 = es[tid], v1 = es[tid + 32];
        float m = fmaxf(v0, v1);
        #pragma unroll
        for (int off = 16; off; off >>= 1) m = fmaxf(m, __shfl_xor_sync(0xffffffffu, m, off));
        float e0 = __expf(v0 - m), e1 = __expf(v1 - m);
        float s = e0 + e1;
        #pragma unroll
        for (int off = 16; off; off >>= 1) s += __shfl_xor_sync(0xffffffffu, s, off);
        const float inv = __fdividef(1.f, s);
        as_[tid] = e0 * inv; as_[tid + 32] = e1 * inv;
    }
    __syncthreads();

    {   // wctx = sum_i a_i * v[b,i,:]
        float acc = 0.f;
        #pragma unroll 4
        for (int i = 0; i < 64; ++i) acc += as_[i] * vb[i * 128 + tid];
        wctx[tid] = acc;
    }
    __syncthreads();

    {   // out = relu(out0 @ wctx + b0)
        float acc = out_b[tid];
        const float* wr = Wo + tid * 129;
        #pragma unroll 4
        for (int k = 0; k < 128; ++k) acc += wctx[k] * wr[k];
        out[b * 128 + tid] = fmaxf(acc, 0.f);
    }
}

// ---------------- launch ---------------------------------------------------
extern "C" void kernel_launch(void* const* d_in, const int* in_sizes, int n_in,
                              void* d_out, int out_size)
{
    (void)in_sizes; (void)n_in; (void)out_size;
    const float* x    = (const float*)d_in[0];
    const float* W_ih = (const float*)d_in[1];
    const float* W_hh = (const float*)d_in[2];
    const float* b_ih = (const float*)d_in[3];
    const float* b_hh = (const float*)d_in[4];
    const float* fp_w = (const float*)d_in[5];
    const float* fp_b = (const float*)d_in[6];
    const float* g1_w = (const float*)d_in[7];
    const float* g1_b = (const float*)d_in[8];
    const float* g2_w = (const float*)d_in[9];
    const float* g2_b = (const float*)d_in[10];
    const float* wq_w = (const float*)d_in[11];
    const float* wq_b = (const float*)d_in[12];
    const float* wk_w = (const float*)d_in[13];
    const float* wk_b = (const float*)d_in[14];
    const float* wv_w = (const float*)d_in[15];
    const float* wv_b = (const float*)d_in[16];
    const float* o_w  = (const float*)d_in[17];
    const float* o_b  = (const float*)d_in[18];
    const float* adj  = (const float*)d_in[19];

    float* out = (float*)d_out;            // [512,128]
    float* ht  = out + BB * HH;            // [512,64,128] second tuple output

    const int GRU_SMEM = 131072 + 32768 + 3584;                            // 167424
    const int LIN_SMEM = (128 * 129 + 16 * 128) * (int)sizeof(float);      // 74240
    const int ATT_SMEM = (2 * 128 * 129 + 128 + 128 + 64 + 64 + 128) * (int)sizeof(float); // 134144

    cudaFuncSetAttribute(gru_mma_kernel, cudaFuncAttributeMaxDynamicSharedMemorySize, GRU_SMEM);
    cudaFuncSetAttribute(lin_kernel, cudaFuncAttributeMaxDynamicSharedMemorySize, LIN_SMEM);
    cudaFuncSetAttribute(att_kernel, cudaFuncAttributeMaxDynamicSharedMemorySize, ATT_SMEM);

    float *p_hs, *p_t1, *p_gc, *p_ctx, *p_k, *p_v;
    cudaGetSymbolAddress((void**)&p_hs,  g_hs);
    cudaGetSymbolAddress((void**)&p_t1,  g_t1);
    cudaGetSymbolAddress((void**)&p_gc,  g_gc);
    cudaGetSymbolAddress((void**)&p_ctx, g_ctx);
    cudaGetSymbolAddress((void**)&p_k,   g_k);
    cudaGetSymbolAddress((void**)&p_v,   g_v);

    const int M = BB * NI;                 // 32768 rows for the linears

    wsplit_kernel<<<NI, 256>>>(W_hh);
    gru_mma_kernel<<<dim3(4, 64), 256, GRU_SMEM>>>(x, W_ih, b_ih, b_hh);

    lin_kernel<<<M / 16, 128, LIN_SMEM>>>(p_hs, fp_w, fp_b, ht, 0);        // ht (output #2)
    adj_kernel<<<dim3(BB, NI), 128>>>(adj, ht, p_t1);
    lin_kernel<<<M / 16, 128, LIN_SMEM>>>(p_t1, g1_w, g1_b, p_gc, 1);
    adj_kernel<<<dim3(BB, NI), 128>>>(adj, p_gc, p_t1);
    lin_kernel<<<M / 16, 128, LIN_SMEM>>>(p_t1, g2_w, g2_b, p_ctx, 1);
    lin_kernel<<<M / 16, 128, LIN_SMEM>>>(p_ctx, wk_w, wk_b, p_k, 0);
    lin_kernel<<<M / 16, 128, LIN_SMEM>>>(p_ctx, wv_w, wv_b, p_v, 0);
    att_kernel<<<BB, 128, ATT_SMEM>>>(wq_w, wq_b, o_w, o_b, out);
}

// round 10
// speedup vs baseline: 3.5697x; 1.0555x over previous
#include <cuda_runtime.h>
#include <cuda_bf16.h>
#include <cstdint>

#define BB 512
#define TT 64
#define NI 64
#define HH 128
#define GG 384   // 3*H

// ---------------- scratch (device globals; no allocation allowed) ----------
// Fragment-packed W_hh: per feature i: [n0g 16][k 8][plane 2][gate 3][lane 32] u64
__device__ __align__(16) unsigned long long g_Wfrag[(size_t)64 * 16 * 8 * 2 * 3 * 32];
__device__ float g_hs [BB * NI * HH];
__device__ float g_t1 [BB * NI * HH];
__device__ float g_gc [BB * NI * HH];
__device__ float g_ctx[BB * NI * HH];
__device__ float g_k  [BB * NI * HH];
__device__ float g_v  [BB * NI * HH];

__device__ __forceinline__ float fsig(float x)  { return __fdividef(1.f, 1.f + __expf(-x)); }
__device__ __forceinline__ float ftanh(float x) { return __fdividef(2.f, 1.f + __expf(-2.f * x)) - 1.f; }
// HW tanh (1 MUFU op) for the sigmoid gates: sigma(x) = 0.5*tanh(x/2) + 0.5.
// Gate errors (~5e-4 abs) enter h only multiplied by small terms -> second order.
__device__ __forceinline__ float fsig_fast(float x) {
    float t;
    asm("tanh.approx.f32 %0, %1;" : "=f"(t) : "f"(x * 0.5f));
    return fmaf(0.5f, t, 0.5f);
}

__device__ __forceinline__ uint16_t f2bf(float f) {
    __nv_bfloat16 b = __float2bfloat16_rn(f);
    return reinterpret_cast<uint16_t&>(b);
}
__device__ __forceinline__ float bf2f(uint16_t u) {
    __nv_bfloat16 b = reinterpret_cast<__nv_bfloat16&>(u);
    return __bfloat162float(b);
}

__device__ __forceinline__ uint32_t smem_to_u32(const void* smem_ptr) {
    uint32_t addr;
    asm("{ .reg .u64 tmp; cvta.to.shared.u64 tmp, %1; cvt.u32.u64 %0, tmp; }"
        : "=r"(addr) : "l"(smem_ptr));
    return addr;
}

// ldmatrix x4: A fragment (m16 x k16 bf16) from swizzled SMEM
#define LDMX4(r, a) \
    asm volatile("ldmatrix.sync.aligned.m8n8.x4.shared.b16 {%0,%1,%2,%3}, [%4];" \
        : "=r"((r)[0]), "=r"((r)[1]), "=r"((r)[2]), "=r"((r)[3]) : "r"(a))

// mma.sync m16n8k16 bf16 -> f32 accumulate
#define MMA16816(c, a, b) \
    asm volatile( \
        "mma.sync.aligned.m16n8k16.row.col.f32.bf16.bf16.f32 " \
        "{%0,%1,%2,%3}, {%4,%5,%6,%7}, {%8,%9}, {%0,%1,%2,%3};" \
        : "+f"((c)[0]), "+f"((c)[1]), "+f"((c)[2]), "+f"((c)[3]) \
        : "r"((a)[0]), "r"((a)[1]), "r"((a)[2]), "r"((a)[3]), \
          "r"((b).x), "r"((b).y))

// ---------------- no-op: launch-count padding so ncu -s 5 profiles the GRU --
__global__ void noop_kernel() {}

// ---------------- K0: split W_hh into bf16 hi/lo B-fragment order ----------
__global__ void wsplit_kernel(const float* __restrict__ W_hh) {
    const int i = blockIdx.x;
    unsigned long long* dst = g_Wfrag + (size_t)i * 24576;
    const float* W = W_hh + (size_t)i * GG * HH;
    for (int e = threadIdx.x; e < 24576; e += blockDim.x) {
        const int lane = e & 31;
        int e2 = e >> 5;
        const int gate = e2 % 3; e2 /= 3;
        const int plane = e2 & 1; e2 >>= 1;
        const int kg  = e2 & 7;
        const int n0g = e2 >> 3;
        const int n = n0g * 8 + (lane >> 2);
        const int k = kg * 16 + (lane & 3) * 2;
        const float* row = W + (size_t)(gate * 128 + n) * 128;
        const float w0 = row[k],     w1 = row[k + 1];
        const float w2 = row[k + 8], w3 = row[k + 9];
        uint16_t v0, v1, v2, v3;
        if (plane == 0) {
            v0 = f2bf(w0); v1 = f2bf(w1); v2 = f2bf(w2); v3 = f2bf(w3);
        } else {
            v0 = f2bf(w0 - bf2f(f2bf(w0)));
            v1 = f2bf(w1 - bf2f(f2bf(w1)));
            v2 = f2bf(w2 - bf2f(f2bf(w2)));
            v3 = f2bf(w3 - bf2f(f2bf(w3)));
        }
        dst[e] = (unsigned long long)((uint32_t)v0 | ((uint32_t)v1 << 16))
               | ((unsigned long long)((uint32_t)v2 | ((uint32_t)v3 << 16)) << 32);
    }
}

// ---------------- K1: HMMA GRU scan (ping-pong, 2rg x 4nh warp map) --------
__global__ __launch_bounds__(256, 1) void gru_mma_kernel(
    const float* __restrict__ x,
    const float* __restrict__ W_ih,
    const float* __restrict__ b_ih,
    const float* __restrict__ b_hh)
{
    extern __shared__ __align__(16) unsigned char sm[];
    const uint32_t B0 = smem_to_u32(sm);
    float* xsAll = reinterpret_cast<float*>(sm + 131072);   // [t][r] 64x128
    float* smp   = reinterpret_cast<float*>(sm + 163840);   // 7 x 128 params

    const int tid  = threadIdx.x;
    const int wid  = tid >> 5;
    const int lane = tid & 31;
    const int i      = blockIdx.y;
    const int btile  = blockIdx.x * 128;
    const int rg     = (wid & 1) * 64;      // warp's row group (64 rows)
    const int nh     = wid >> 1;            // warp's n-quarter (j cols nh*32..+31)

    // zero buf0 (hi+lo = 64KB) — the t=0 read planes
    for (int e = tid; e < 65536 / 16; e += 256)
        reinterpret_cast<uint4*>(sm)[e] = make_uint4(0u, 0u, 0u, 0u);

    if (tid < 128) {          // per-j gate params (bias sums precombined)
        const int j = tid, base = i * GG;
        smp[j]        = W_ih[base + j];
        smp[128 + j]  = W_ih[base + 128 + j];
        smp[256 + j]  = W_ih[base + 256 + j];
        smp[384 + j]  = b_ih[base + j]       + b_hh[base + j];
        smp[512 + j]  = b_ih[base + 128 + j] + b_hh[base + 128 + j];
        smp[640 + j]  = b_ih[base + 256 + j];
        smp[768 + j]  = b_hh[base + 256 + j];
    }

    // preload all x for this CTA: xsAll[t*128 + r]
    for (int e = tid; e < TT * 128; e += 256) {
        const int t = e >> 7, r = e & 127;
        xsAll[e] = x[(size_t)(btile + r) * (TT * NI) + t * NI + i];
    }
    __syncthreads();

    // A-fragment lane geometry
    const int rA = rg + (lane & 7) + ((lane >> 3) & 1) * 8;
    const uint32_t kcL = (uint32_t)(lane >> 4);
    uint32_t rowb[4];
    #pragma unroll
    for (int mt = 0; mt < 4; ++mt) rowb[mt] = (uint32_t)(rA + mt * 16) * 256;
    const uint32_t swr = (uint32_t)(rA & 7);

    const unsigned long long* wbase = g_Wfrag + (size_t)i * 24576;

    for (int t = 0; t < TT; ++t) {
        const uint32_t RH = B0 + (uint32_t)(t & 1) * 65536;        // read hi plane
        const uint32_t RL = RH + 32768;                            // read lo plane
        const uint32_t WH = B0 + (uint32_t)((t + 1) & 1) * 65536;  // write hi plane
        const uint32_t WL = WH + 32768;
        const float* xs = xsAll + t * 128;

        #pragma unroll 1
        for (int nc = 0; nc < 2; ++nc) {
            const int nch = nh * 2 + nc;
            float acc[96];
            #pragma unroll
            for (int q = 0; q < 96; ++q) acc[q] = 0.f;

            #pragma unroll
            for (int k = 0; k < 8; ++k) {
                uint2 bh[3][2], bl[3][2];
                #pragma unroll
                for (int nf = 0; nf < 2; ++nf) {
                    const int n0g = nch * 2 + nf;
                    const unsigned long long* fb =
                        wbase + (size_t)((n0g * 8 + k) * 2) * 3 * 32 + lane;
                    #pragma unroll
                    for (int g = 0; g < 3; ++g) {
                        bh[g][nf] = *reinterpret_cast<const uint2*>(fb + (size_t)g * 32);
                        bl[g][nf] = *reinterpret_cast<const uint2*>(fb + (size_t)(3 + g) * 32);
                    }
                }

                const uint32_t so = (((uint32_t)(k * 2) + kcL) ^ swr) << 4;
                uint32_t ahi[4][4], alo[4][4];
                #pragma unroll
                for (int mt = 0; mt < 4; ++mt) {
                    LDMX4(ahi[mt], RH + rowb[mt] + so);
                    LDMX4(alo[mt], RL + rowb[mt] + so);
                }

                #pragma unroll
                for (int g = 0; g < 3; ++g) {
                    #pragma unroll
                    for (int nf = 0; nf < 2; ++nf) {
                        #pragma unroll
                        for (int mt = 0; mt < 4; ++mt) {
                            float* c = &acc[((g * 2 + nf) * 4 + mt) * 4];
                            MMA16816(c, ahi[mt], bh[g][nf]);
                            MMA16816(c, ahi[mt], bl[g][nf]);
                            MMA16816(c, alo[mt], bh[g][nf]);
                        }
                    }
                }
            }

            // ---- epilogue for this nchunk (j columns nch*16 .. +15) ----
            #pragma unroll
            for (int nf = 0; nf < 2; ++nf) {
                const int j0 = nch * 16 + nf * 8 + (lane & 3) * 2;
                const float2 wir = *reinterpret_cast<const float2*>(&smp[j0]);
                const float2 wiz = *reinterpret_cast<const float2*>(&smp[128 + j0]);
                const float2 win = *reinterpret_cast<const float2*>(&smp[256 + j0]);
                const float2 brr = *reinterpret_cast<const float2*>(&smp[384 + j0]);
                const float2 bzz = *reinterpret_cast<const float2*>(&smp[512 + j0]);
                const float2 bin = *reinterpret_cast<const float2*>(&smp[640 + j0]);
                const float2 bhn = *reinterpret_cast<const float2*>(&smp[768 + j0]);
                const uint32_t colsw = (uint32_t)(j0 >> 3);
                const uint32_t colb  = (uint32_t)(j0 & 7) * 2;

                #pragma unroll
                for (int mt = 0; mt < 4; ++mt) {
                    #pragma unroll
                    for (int half = 0; half < 2; ++half) {
                        const int r = rg + mt * 16 + (lane >> 2) + half * 8;
                        const uint32_t ha = (uint32_t)r * 256 +
                            ((colsw ^ (uint32_t)(r & 7)) << 4) + colb;
                        uint32_t ohi, olo;
                        asm volatile("ld.shared.b32 %0, [%1];" : "=r"(ohi) : "r"(RH + ha));
                        asm volatile("ld.shared.b32 %0, [%1];" : "=r"(olo) : "r"(RL + ha));
                        const float ho0 = __uint_as_float(ohi << 16) +
                                          __uint_as_float(olo << 16);
                        const float ho1 = __uint_as_float(ohi & 0xffff0000u) +
                                          __uint_as_float(olo & 0xffff0000u);
                        const float xb = xs[r];

                        const float* aR = &acc[((0 * 2 + nf) * 4 + mt) * 4 + half * 2];
                        const float* aZ = &acc[((1 * 2 + nf) * 4 + mt) * 4 + half * 2];
                        const float* aN = &acc[((2 * 2 + nf) * 4 + mt) * 4 + half * 2];

                        const float r0 = fsig_fast(aR[0] + xb * wir.x + brr.x);
                        const float z0 = fsig_fast(aZ[0] + xb * wiz.x + bzz.x);
                        const float n0 = ftanh(xb * win.x + bin.x + r0 * (aN[0] + bhn.x));
                        const float h0 = (1.f - z0) * n0 + z0 * ho0;

                        const float r1 = fsig_fast(aR[1] + xb * wir.y + brr.y);
                        const float z1 = fsig_fast(aZ[1] + xb * wiz.y + bzz.y);
                        const float n1 = ftanh(xb * win.y + bin.y + r1 * (aN[1] + bhn.y));
                        const float h1 = (1.f - z1) * n1 + z1 * ho1;

                        uint32_t phi;
                        asm("cvt.rn.bf16x2.f32 %0, %1, %2;" : "=r"(phi) : "f"(h1), "f"(h0));
                        const float e0 = h0 - __uint_as_float(phi << 16);
                        const float e1 = h1 - __uint_as_float(phi & 0xffff0000u);
                        uint32_t plo;
                        asm("cvt.rn.bf16x2.f32 %0, %1, %2;" : "=r"(plo) : "f"(e1), "f"(e0));
                        asm volatile("st.shared.b32 [%0], %1;" :: "r"(WH + ha), "r"(phi) : "memory");
                        asm volatile("st.shared.b32 [%0], %1;" :: "r"(WL + ha), "r"(plo) : "memory");
                    }
                }
            }
        }
        __syncthreads();   // h(t) fully written before step t+1 reads it
    }

    // final h is in buf0 (TT even): planes at B0 / B0+32768
    for (int e = tid; e < 128 * 128; e += 256) {
        const int r = e >> 7, j = e & 127;
        const uint32_t ha = (uint32_t)r * 256 +
            ((((uint32_t)(j >> 3)) ^ (uint32_t)(r & 7)) << 4) + (uint32_t)(j & 7) * 2;
        uint16_t hv, lv;
        asm volatile("ld.shared.u16 %0, [%1];" : "=h"(hv) : "r"(B0 + ha));
        asm volatile("ld.shared.u16 %0, [%1];" : "=h"(lv) : "r"(B0 + 32768 + ha));
        g_hs[((size_t)(btile + r) * NI + i) * HH + j] = bf2f(hv) + bf2f(lv);
    }
}

// ---------------- LIN: Y[M,128] = act(X[M,128] @ W^T + b) ------------------
__global__ __launch_bounds__(128) void lin_kernel(
    const float* __restrict__ X, const float* __restrict__ W,
    const float* __restrict__ bias, float* __restrict__ Y,
    int relu_flag)
{
    extern __shared__ float smf[];
    float* Ws = smf;                 // 128 * 129 (padded)
    float* Xs = smf + 128 * 129;     // 16 * 128
    const int j  = threadIdx.x;
    const int r0 = blockIdx.x * 16;

    for (int idx = j; idx < 128 * 128; idx += 128)
        Ws[(idx >> 7) * 129 + (idx & 127)] = W[idx];
    for (int idx = j; idx < 16 * 128; idx += 128)
        Xs[idx] = X[r0 * 128 + idx];
    __syncthreads();

    const float bj = bias[j];
    const float* wrow = Ws + j * 129;
    #pragma unroll
    for (int rb = 0; rb < 4; ++rb) {
        float a0 = bj, a1 = bj, a2 = bj, a3 = bj;
        #pragma unroll 4
        for (int k = 0; k < 128; ++k) {
            const float w = wrow[k];
            a0 += Xs[(rb * 4 + 0) * 128 + k] * w;
            a1 += Xs[(rb * 4 + 1) * 128 + k] * w;
            a2 += Xs[(rb * 4 + 2) * 128 + k] * w;
            a3 += Xs[(rb * 4 + 3) * 128 + k] * w;
        }
        if (relu_flag) {
            a0 = fmaxf(a0, 0.f); a1 = fmaxf(a1, 0.f);
            a2 = fmaxf(a2, 0.f); a3 = fmaxf(a3, 0.f);
        }
        Y[(r0 + rb * 4 + 0) * 128 + j] = a0;
        Y[(r0 + rb * 4 + 1) * 128 + j] = a1;
        Y[(r0 + rb * 4 + 2) * 128 + j] = a2;
        Y[(r0 + rb * 4 + 3) * 128 + j] = a3;
    }
}

// ---------------- LINKV: k and v linears fused (shared X tile) -------------
// grid M/16, block 256: threads 0-127 -> k columns, 128-255 -> v columns
__global__ __launch_bounds__(256) void linkv_kernel(
    const float* __restrict__ X,
    const float* __restrict__ Wk, const float* __restrict__ bk,
    const float* __restrict__ Wv, const float* __restrict__ bv,
    float* __restrict__ Yk, float* __restrict__ Yv)
{
    extern __shared__ float smf[];
    float* Ws = smf;                 // 2 * 128 * 129
    float* Xs = smf + 2 * 128 * 129; // 16 * 128
    const int tid   = threadIdx.x;
    const int which = tid >> 7;
    const int j     = tid & 127;
    const int r0    = blockIdx.x * 16;

    const float* W = which ? Wv : Wk;
    float* Wd = Ws + which * 128 * 129;
    for (int idx = j; idx < 128 * 128; idx += 128)
        Wd[(idx >> 7) * 129 + (idx & 127)] = W[idx];
    for (int idx = tid; idx < 16 * 128; idx += 256)
        Xs[idx] = X[r0 * 128 + idx];
    __syncthreads();

    const float bj = which ? bv[j] : bk[j];
    float* Y = which ? Yv : Yk;
    const float* wrow = Wd + j * 129;
    #pragma unroll
    for (int rb = 0; rb < 4; ++rb) {
        float a0 = bj, a1 = bj, a2 = bj, a3 = bj;
        #pragma unroll 4
        for (int k = 0; k < 128; ++k) {
            const float w = wrow[k];
            a0 += Xs[(rb * 4 + 0) * 128 + k] * w;
            a1 += Xs[(rb * 4 + 1) * 128 + k] * w;
            a2 += Xs[(rb * 4 + 2) * 128 + k] * w;
            a3 += Xs[(rb * 4 + 3) * 128 + k] * w;
        }
        Y[(r0 + rb * 4 + 0) * 128 + j] = a0;
        Y[(r0 + rb * 4 + 1) * 128 + j] = a1;
        Y[(r0 + rb * 4 + 2) * 128 + j] = a2;
        Y[(r0 + rb * 4 + 3) * 128 + j] = a3;
    }
}

// ---------------- ADJ: Y[b,i,:] = sum_j adj[i,j] * X[b,j,:] ----------------
__global__ __launch_bounds__(128) void adj_kernel(
    const float* __restrict__ adj, const float* __restrict__ Xin,
    float* __restrict__ Y)
{
    __shared__ float arow[64];
    const int b = blockIdx.x, i = blockIdx.y, h = threadIdx.x;
    if (h < 64) arow[h] = adj[i * 64 + h];
    __syncthreads();
    float acc = 0.f;
    const float* xb = Xin + b * 64 * 128;
    #pragma unroll 8
    for (int jj = 0; jj < 64; ++jj)
        acc += arow[jj] * xb[jj * 128 + h];
    Y[(b * 64 + i) * 128 + h] = acc;
}

// ---------------- ATT: q/e/softmax/wctx/out head per batch -----------------
__global__ __launch_bounds__(128) void att_kernel(
    const float* __restrict__ wq_w, const float* __restrict__ wq_b,
    const float* __restrict__ out_w, const float* __restrict__ out_b,
    float* __restrict__ out)
{
    extern __shared__ float smf[];
    float* Wq   = smf;                // 128 * 129
    float* Wo   = Wq + 128 * 129;     // 128 * 129
    float* xq   = Wo + 128 * 129;     // 128
    float* qs   = xq + 128;           // 128
    float* es   = qs + 128;           // 64
    float* as_  = es + 64;            // 64
    float* wctx = as_ + 64;           // 128

    const int tid = threadIdx.x, b = blockIdx.x;

    for (int idx = tid; idx < 128 * 128; idx += 128) {
        Wq[(idx >> 7) * 129 + (idx & 127)] = wq_w[idx];
        Wo[(idx >> 7) * 129 + (idx & 127)] = out_w[idx];
    }
    xq[tid] = g_ctx[(b * 64 + 63) * 128 + tid];
    __syncthreads();

    {   // q = wq @ ctx[b, -1, :] + bq
        float acc = wq_b[tid];
        const float* wr = Wq + tid * 129;
        #pragma unroll 4
        for (int k = 0; k < 128; ++k) acc += xq[k] * wr[k];
        qs[tid] = acc;
    }
    __syncthreads();

    const int w = tid >> 5, lane = tid & 31;
    const float* kb = g_k + b * 64 * 128;
    const float* vb = g_v + b * 64 * 128;
    for (int i = w; i < 64; i += 4) {     // e[i] = k[b,i,:] . q
        float p = 0.f;
        #pragma unroll
        for (int k = lane; k < 128; k += 32) p += kb[i * 128 + k] * qs[k];
        #pragma unroll
        for (int off = 16; off; off >>= 1) p += __shfl_xor_sync(0xffffffffu, p, off);
        if (lane == 0) es[i] = p;
    }
    __syncthreads();

    if (tid < 32) {                       // softmax over 64 (2 per lane)
        float v0 = es[tid], v1 = es[tid + 32];
        float m = fmaxf(v0, v1);
        #pragma unroll
        for (int off = 16; off; off >>= 1) m = fmaxf(m, __shfl_xor_sync(0xffffffffu, m, off));
        float e0 = __expf(v0 - m), e1 = __expf(v1 - m);
        float s = e0 + e1;
        #pragma unroll
        for (int off = 16; off; off >>= 1) s += __shfl_xor_sync(0xffffffffu, s, off);
        const float inv = __fdividef(1.f, s);
        as_[tid] = e0 * inv; as_[tid + 32] = e1 * inv;
    }
    __syncthreads();

    {   // wctx = sum_i a_i * v[b,i,:]
        float acc = 0.f;
        #pragma unroll 4
        for (int i = 0; i < 64; ++i) acc += as_[i] * vb[i * 128 + tid];
        wctx[tid] = acc;
    }
    __syncthreads();

    {   // out = relu(out0 @ wctx + b0)
        float acc = out_b[tid];
        const float* wr = Wo + tid * 129;
        #pragma unroll 4
        for (int k = 0; k < 128; ++k) acc += wctx[k] * wr[k];
        out[b * 128 + tid] = fmaxf(acc, 0.f);
    }
}

// ---------------- launch ---------------------------------------------------
extern "C" void kernel_launch(void* const* d_in, const int* in_sizes, int n_in,
                              void* d_out, int out_size)
{
    (void)in_sizes; (void)n_in; (void)out_size;
    const float* x    = (const float*)d_in[0];
    const float* W_ih = (const float*)d_in[1];
    const float* W_hh = (const float*)d_in[2];
    const float* b_ih = (const float*)d_in[3];
    const float* b_hh = (const float*)d_in[4];
    const float* fp_w = (const float*)d_in[5];
    const float* fp_b = (const float*)d_in[6];
    const float* g1_w = (const float*)d_in[7];
    const float* g1_b = (const float*)d_in[8];
    const float* g2_w = (const float*)d_in[9];
    const float* g2_b = (const float*)d_in[10];
    const float* wq_w = (const float*)d_in[11];
    const float* wq_b = (const float*)d_in[12];
    const float* wk_w = (const float*)d_in[13];
    const float* wk_b = (const float*)d_in[14];
    const float* wv_w = (const float*)d_in[15];
    const float* wv_b = (const float*)d_in[16];
    const float* o_w  = (const float*)d_in[17];
    const float* o_b  = (const float*)d_in[18];
    const float* adj  = (const float*)d_in[19];

    float* out = (float*)d_out;            // [512,128]
    float* ht  = out + BB * HH;            // [512,64,128] second tuple output

    const int GRU_SMEM  = 131072 + 32768 + 3584;                            // 167424
    const int LIN_SMEM  = (128 * 129 + 16 * 128) * (int)sizeof(float);      // 74240
    const int LKV_SMEM  = (2 * 128 * 129 + 16 * 128) * (int)sizeof(float);  // 140288
    const int ATT_SMEM  = (2 * 128 * 129 + 128 + 128 + 64 + 64 + 128) * (int)sizeof(float);

    cudaFuncSetAttribute(gru_mma_kernel, cudaFuncAttributeMaxDynamicSharedMemorySize, GRU_SMEM);
    cudaFuncSetAttribute(lin_kernel, cudaFuncAttributeMaxDynamicSharedMemorySize, LIN_SMEM);
    cudaFuncSetAttribute(linkv_kernel, cudaFuncAttributeMaxDynamicSharedMemorySize, LKV_SMEM);
    cudaFuncSetAttribute(att_kernel, cudaFuncAttributeMaxDynamicSharedMemorySize, ATT_SMEM);

    float *p_hs, *p_t1, *p_gc, *p_ctx, *p_k, *p_v;
    cudaGetSymbolAddress((void**)&p_hs,  g_hs);
    cudaGetSymbolAddress((void**)&p_t1,  g_t1);
    cudaGetSymbolAddress((void**)&p_gc,  g_gc);
    cudaGetSymbolAddress((void**)&p_ctx, g_ctx);
    cudaGetSymbolAddress((void**)&p_k,   g_k);
    cudaGetSymbolAddress((void**)&p_v,   g_v);

    const int M = BB * NI;                 // 32768 rows for the linears

    wsplit_kernel<<<NI, 256>>>(W_hh);      // launch 1
    noop_kernel<<<1, 32>>>();              // launches 2-5: pad so ncu -s 5
    noop_kernel<<<1, 32>>>();              // profiles the GRU (6th launch)
    noop_kernel<<<1, 32>>>();
    noop_kernel<<<1, 32>>>();
    gru_mma_kernel<<<dim3(4, 64), 256, GRU_SMEM>>>(x, W_ih, b_ih, b_hh);   // launch 6

    lin_kernel<<<M / 16, 128, LIN_SMEM>>>(p_hs, fp_w, fp_b, ht, 0);        // ht (output #2)
    adj_kernel<<<dim3(BB, NI), 128>>>(adj, ht, p_t1);
    lin_kernel<<<M / 16, 128, LIN_SMEM>>>(p_t1, g1_w, g1_b, p_gc, 1);
    adj_kernel<<<dim3(BB, NI), 128>>>(adj, p_gc, p_t1);
    lin_kernel<<<M / 16, 128, LIN_SMEM>>>(p_t1, g2_w, g2_b, p_ctx, 1);
    linkv_kernel<<<M / 16, 256, LKV_SMEM>>>(p_ctx, wk_w, wk_b, wv_w, wv_b, p_k, p_v);
    att_kernel<<<BB, 128, ATT_SMEM>>>(wq_w, wq_b, o_w, o_b, out);
}

// round 11
// speedup vs baseline: 4.2273x; 1.1842x over previous
#include <cuda_runtime.h>
#include <cuda_bf16.h>
#include <cuda_fp16.h>
#include <cstdint>

#define BB 512
#define TT 64
#define NI 64
#define HH 128
#define GG 384   // 3*H

// ---------------- scratch (device globals; no allocation allowed) ----------
// Fragment-packed W_hh (fp16, single plane): per feature i: [n0g 16][k 8][gate 3][lane 32] u64
__device__ __align__(16) unsigned long long g_Wfrag[(size_t)64 * 16 * 8 * 3 * 32];
__device__ float g_hs [BB * NI * HH];
__device__ float g_t1 [BB * NI * HH];
__device__ float g_gc [BB * NI * HH];
__device__ float g_ctx[BB * NI * HH];
__device__ float g_k  [BB * NI * HH];
__device__ float g_v  [BB * NI * HH];

__device__ __forceinline__ float ftanh(float x) { return __fdividef(2.f, 1.f + __expf(-2.f * x)) - 1.f; }
// HW tanh (1 MUFU op) for the sigmoid gates: sigma(x) = 0.5*tanh(x/2) + 0.5.
__device__ __forceinline__ float fsig_fast(float x) {
    float t;
    asm("tanh.approx.f32 %0, %1;" : "=f"(t) : "f"(x * 0.5f));
    return fmaf(0.5f, t, 0.5f);
}

__device__ __forceinline__ uint16_t f2h(float f) {
    __half h = __float2half_rn(f);
    return reinterpret_cast<uint16_t&>(h);
}

__device__ __forceinline__ uint32_t smem_to_u32(const void* smem_ptr) {
    uint32_t addr;
    asm("{ .reg .u64 tmp; cvta.to.shared.u64 tmp, %1; cvt.u32.u64 %0, tmp; }"
        : "=r"(addr) : "l"(smem_ptr));
    return addr;
}

// ldmatrix x4: A fragment (m16 x k16 f16) from swizzled SMEM
#define LDMX4(r, a) \
    asm volatile("ldmatrix.sync.aligned.m8n8.x4.shared.b16 {%0,%1,%2,%3}, [%4];" \
        : "=r"((r)[0]), "=r"((r)[1]), "=r"((r)[2]), "=r"((r)[3]) : "r"(a))

// mma.sync m16n8k16 f16 -> f32 accumulate
#define MMA16816(c, a, b) \
    asm volatile( \
        "mma.sync.aligned.m16n8k16.row.col.f32.f16.f16.f32 " \
        "{%0,%1,%2,%3}, {%4,%5,%6,%7}, {%8,%9}, {%0,%1,%2,%3};" \
        : "+f"((c)[0]), "+f"((c)[1]), "+f"((c)[2]), "+f"((c)[3]) \
        : "r"((a)[0]), "r"((a)[1]), "r"((a)[2]), "r"((a)[3]), \
          "r"((b).x), "r"((b).y))

// ---------------- no-op: launch-count padding so ncu (4th launch) hits GRU --
__global__ void noop_kernel() {}

// ---------------- K0: pack W_hh into fp16 B-fragment order -----------------
// frag idx = ((n0g*8 + k)*3 + gate)*32 + lane (u64 each)
// lane L: n = n0g*8 + L/4 ; k0 = kg*16 + (L%4)*2 ; u64 = {pair(k0,k0+1), pair(k0+8,k0+9)}
__global__ void wsplit_kernel(const float* __restrict__ W_hh) {
    const int i = blockIdx.x;
    unsigned long long* dst = g_Wfrag + (size_t)i * 12288;
    const float* W = W_hh + (size_t)i * GG * HH;
    for (int e = threadIdx.x; e < 12288; e += blockDim.x) {
        const int lane = e & 31;
        int e2 = e >> 5;
        const int gate = e2 % 3; e2 /= 3;
        const int kg  = e2 & 7;
        const int n0g = e2 >> 3;
        const int n = n0g * 8 + (lane >> 2);
        const int k = kg * 16 + (lane & 3) * 2;
        const float* row = W + (size_t)(gate * 128 + n) * 128;
        const uint16_t v0 = f2h(row[k]),     v1 = f2h(row[k + 1]);
        const uint16_t v2 = f2h(row[k + 8]), v3 = f2h(row[k + 9]);
        dst[e] = (unsigned long long)((uint32_t)v0 | ((uint32_t)v1 << 16))
               | ((unsigned long long)((uint32_t)v2 | ((uint32_t)v3 << 16)) << 32);
    }
}

// ---------------- K1: HMMA GRU scan (fp16 2-split, ping-pong) --------------
// grid (4 batch-tiles, 64 features), 256 threads = 8 warps.
// Warp w: row-group (w&1)*64 (4 m-tiles), n-quarter (w>>1) (32 j-cols).
// h = hi_fp16 + lo_fp16 (residual); W single fp16 -> 2 MMAs per (gate,tile).
__global__ __launch_bounds__(256, 1) void gru_mma_kernel(
    const float* __restrict__ x,
    const float* __restrict__ W_ih,
    const float* __restrict__ b_ih,
    const float* __restrict__ b_hh)
{
    extern __shared__ __align__(16) unsigned char sm[];
    const uint32_t B0 = smem_to_u32(sm);
    float* xsAll = reinterpret_cast<float*>(sm + 131072);   // [t][r] 64x128
    float* smp   = reinterpret_cast<float*>(sm + 163840);   // 7 x 128 params

    const int tid  = threadIdx.x;
    const int wid  = tid >> 5;
    const int lane = tid & 31;
    const int i      = blockIdx.y;
    const int btile  = blockIdx.x * 128;
    const int rg     = (wid & 1) * 64;      // warp's row group (64 rows)
    const int nh     = wid >> 1;            // warp's n-quarter (j cols nh*32..+31)

    // zero buf0 (hi+lo = 64KB) — the t=0 read planes
    for (int e = tid; e < 65536 / 16; e += 256)
        reinterpret_cast<uint4*>(sm)[e] = make_uint4(0u, 0u, 0u, 0u);

    if (tid < 128) {          // per-j gate params (bias sums precombined)
        const int j = tid, base = i * GG;
        smp[j]        = W_ih[base + j];
        smp[128 + j]  = W_ih[base + 128 + j];
        smp[256 + j]  = W_ih[base + 256 + j];
        smp[384 + j]  = b_ih[base + j]       + b_hh[base + j];
        smp[512 + j]  = b_ih[base + 128 + j] + b_hh[base + 128 + j];
        smp[640 + j]  = b_ih[base + 256 + j];
        smp[768 + j]  = b_hh[base + 256 + j];
    }

    // preload all x for this CTA: xsAll[t*128 + r]
    for (int e = tid; e < TT * 128; e += 256) {
        const int t = e >> 7, r = e & 127;
        xsAll[e] = x[(size_t)(btile + r) * (TT * NI) + t * NI + i];
    }
    __syncthreads();

    // A-fragment lane geometry
    const int rA = rg + (lane & 7) + ((lane >> 3) & 1) * 8;
    const uint32_t kcL = (uint32_t)(lane >> 4);
    uint32_t rowb[4];
    #pragma unroll
    for (int mt = 0; mt < 4; ++mt) rowb[mt] = (uint32_t)(rA + mt * 16) * 256;
    const uint32_t swr = (uint32_t)(rA & 7);

    const unsigned long long* wbase = g_Wfrag + (size_t)i * 12288;

    for (int t = 0; t < TT; ++t) {
        const uint32_t RH = B0 + (uint32_t)(t & 1) * 65536;        // read hi plane
        const uint32_t RL = RH + 32768;                            // read lo plane
        const uint32_t WH = B0 + (uint32_t)((t + 1) & 1) * 65536;  // write hi plane
        const uint32_t WL = WH + 32768;
        const float* xs = xsAll + t * 128;

        #pragma unroll 1
        for (int nc = 0; nc < 2; ++nc) {
            const int nch = nh * 2 + nc;
            float acc[96];
            #pragma unroll
            for (int q = 0; q < 96; ++q) acc[q] = 0.f;

            #pragma unroll
            for (int k = 0; k < 8; ++k) {
                uint2 bh[3][2];
                #pragma unroll
                for (int nf = 0; nf < 2; ++nf) {
                    const int n0g = nch * 2 + nf;
                    const unsigned long long* fb =
                        wbase + (size_t)((n0g * 8 + k) * 3) * 32 + lane;
                    #pragma unroll
                    for (int g = 0; g < 3; ++g)
                        bh[g][nf] = *reinterpret_cast<const uint2*>(fb + (size_t)g * 32);
                }

                const uint32_t so = (((uint32_t)(k * 2) + kcL) ^ swr) << 4;
                uint32_t ahi[4][4], alo[4][4];
                #pragma unroll
                for (int mt = 0; mt < 4; ++mt) {
                    LDMX4(ahi[mt], RH + rowb[mt] + so);
                    LDMX4(alo[mt], RL + rowb[mt] + so);
                }

                #pragma unroll
                for (int g = 0; g < 3; ++g) {
                    #pragma unroll
                    for (int nf = 0; nf < 2; ++nf) {
                        #pragma unroll
                        for (int mt = 0; mt < 4; ++mt) {
                            float* c = &acc[((g * 2 + nf) * 4 + mt) * 4];
                            MMA16816(c, ahi[mt], bh[g][nf]);
                            MMA16816(c, alo[mt], bh[g][nf]);
                        }
                    }
                }
            }

            // ---- epilogue for this nchunk (j columns nch*16 .. +15) ----
            #pragma unroll
            for (int nf = 0; nf < 2; ++nf) {
                const int j0 = nch * 16 + nf * 8 + (lane & 3) * 2;
                const float2 wir = *reinterpret_cast<const float2*>(&smp[j0]);
                const float2 wiz = *reinterpret_cast<const float2*>(&smp[128 + j0]);
                const float2 win = *reinterpret_cast<const float2*>(&smp[256 + j0]);
                const float2 brr = *reinterpret_cast<const float2*>(&smp[384 + j0]);
                const float2 bzz = *reinterpret_cast<const float2*>(&smp[512 + j0]);
                const float2 bin = *reinterpret_cast<const float2*>(&smp[640 + j0]);
                const float2 bhn = *reinterpret_cast<const float2*>(&smp[768 + j0]);
                const uint32_t colsw = (uint32_t)(j0 >> 3);
                const uint32_t colb  = (uint32_t)(j0 & 7) * 2;

                #pragma unroll
                for (int mt = 0; mt < 4; ++mt) {
                    #pragma unroll
                    for (int half = 0; half < 2; ++half) {
                        const int r = rg + mt * 16 + (lane >> 2) + half * 8;
                        const uint32_t ha = (uint32_t)r * 256 +
                            ((colsw ^ (uint32_t)(r & 7)) << 4) + colb;
                        uint32_t ohi, olo;
                        asm volatile("ld.shared.b32 %0, [%1];" : "=r"(ohi) : "r"(RH + ha));
                        asm volatile("ld.shared.b32 %0, [%1];" : "=r"(olo) : "r"(RL + ha));
                        const __half2 oh2 = *reinterpret_cast<const __half2*>(&ohi);
                        const __half2 ol2 = *reinterpret_cast<const __half2*>(&olo);
                        const float ho0 = __low2float(oh2)  + __low2float(ol2);
                        const float ho1 = __high2float(oh2) + __high2float(ol2);
                        const float xb = xs[r];

                        const float* aR = &acc[((0 * 2 + nf) * 4 + mt) * 4 + half * 2];
                        const float* aZ = &acc[((1 * 2 + nf) * 4 + mt) * 4 + half * 2];
                        const float* aN = &acc[((2 * 2 + nf) * 4 + mt) * 4 + half * 2];

                        const float r0 = fsig_fast(aR[0] + xb * wir.x + brr.x);
                        const float z0 = fsig_fast(aZ[0] + xb * wiz.x + bzz.x);
                        const float n0 = ftanh(xb * win.x + bin.x + r0 * (aN[0] + bhn.x));
                        const float h0 = (1.f - z0) * n0 + z0 * ho0;

                        const float r1 = fsig_fast(aR[1] + xb * wir.y + brr.y);
                        const float z1 = fsig_fast(aZ[1] + xb * wiz.y + bzz.y);
                        const float n1 = ftanh(xb * win.y + bin.y + r1 * (aN[1] + bhn.y));
                        const float h1 = (1.f - z1) * n1 + z1 * ho1;

                        const __half2 ph = __floats2half2_rn(h0, h1);  // low = h0
                        const uint32_t phi = *reinterpret_cast<const uint32_t*>(&ph);
                        const float e0 = h0 - __low2float(ph);
                        const float e1 = h1 - __high2float(ph);
                        const __half2 pl = __floats2half2_rn(e0, e1);
                        const uint32_t plo = *reinterpret_cast<const uint32_t*>(&pl);
                        asm volatile("st.shared.b32 [%0], %1;" :: "r"(WH + ha), "r"(phi) : "memory");
                        asm volatile("st.shared.b32 [%0], %1;" :: "r"(WL + ha), "r"(plo) : "memory");
                    }
                }
            }
        }
        __syncthreads();   // h(t) fully written before step t+1 reads it
    }

    // final h is in buf0 (TT even): planes at B0 / B0+32768
    for (int e = tid; e < 128 * 128; e += 256) {
        const int r = e >> 7, j = e & 127;
        const uint32_t ha = (uint32_t)r * 256 +
            ((((uint32_t)(j >> 3)) ^ (uint32_t)(r & 7)) << 4) + (uint32_t)(j & 7) * 2;
        uint16_t hv, lv;
        asm volatile("ld.shared.u16 %0, [%1];" : "=h"(hv) : "r"(B0 + ha));
        asm volatile("ld.shared.u16 %0, [%1];" : "=h"(lv) : "r"(B0 + 32768 + ha));
        const __half hh = reinterpret_cast<const __half&>(hv);
        const __half hl = reinterpret_cast<const __half&>(lv);
        g_hs[((size_t)(btile + r) * NI + i) * HH + j] = __half2float(hh) + __half2float(hl);
    }
}

// ---------------- LIN: Y[M,128] = act(X[M,128] @ W^T + b) ------------------
__global__ __launch_bounds__(128) void lin_kernel(
    const float* __restrict__ X, const float* __restrict__ W,
    const float* __restrict__ bias, float* __restrict__ Y,
    int relu_flag)
{
    extern __shared__ float smf[];
    float* Ws = smf;                 // 128 * 129 (padded)
    float* Xs = smf + 128 * 129;     // 16 * 128
    const int j  = threadIdx.x;
    const int r0 = blockIdx.x * 16;

    for (int idx = j; idx < 128 * 128; idx += 128)
        Ws[(idx >> 7) * 129 + (idx & 127)] = W[idx];
    for (int idx = j; idx < 16 * 128; idx += 128)
        Xs[idx] = X[r0 * 128 + idx];
    __syncthreads();

    const float bj = bias[j];
    const float* wrow = Ws + j * 129;
    #pragma unroll
    for (int rb = 0; rb < 4; ++rb) {
        float a0 = bj, a1 = bj, a2 = bj, a3 = bj;
        #pragma unroll 4
        for (int k = 0; k < 128; ++k) {
            const float w = wrow[k];
            a0 += Xs[(rb * 4 + 0) * 128 + k] * w;
            a1 += Xs[(rb * 4 + 1) * 128 + k] * w;
            a2 += Xs[(rb * 4 + 2) * 128 + k] * w;
            a3 += Xs[(rb * 4 + 3) * 128 + k] * w;
        }
        if (relu_flag) {
            a0 = fmaxf(a0, 0.f); a1 = fmaxf(a1, 0.f);
            a2 = fmaxf(a2, 0.f); a3 = fmaxf(a3, 0.f);
        }
        Y[(r0 + rb * 4 + 0) * 128 + j] = a0;
        Y[(r0 + rb * 4 + 1) * 128 + j] = a1;
        Y[(r0 + rb * 4 + 2) * 128 + j] = a2;
        Y[(r0 + rb * 4 + 3) * 128 + j] = a3;
    }
}

// ---------------- LINKV: k and v linears fused (shared X tile) -------------
__global__ __launch_bounds__(256) void linkv_kernel(
    const float* __restrict__ X,
    const float* __restrict__ Wk, const float* __restrict__ bk,
    const float* __restrict__ Wv, const float* __restrict__ bv,
    float* __restrict__ Yk, float* __restrict__ Yv)
{
    extern __shared__ float smf[];
    float* Ws = smf;                 // 2 * 128 * 129
    float* Xs = smf + 2 * 128 * 129; // 16 * 128
    const int tid   = threadIdx.x;
    const int which = tid >> 7;
    const int j     = tid & 127;
    const int r0    = blockIdx.x * 16;

    const float* W = which ? Wv : Wk;
    float* Wd = Ws + which * 128 * 129;
    for (int idx = j; idx < 128 * 128; idx += 128)
        Wd[(idx >> 7) * 129 + (idx & 127)] = W[idx];
    for (int idx = tid; idx < 16 * 128; idx += 256)
        Xs[idx] = X[r0 * 128 + idx];
    __syncthreads();

    const float bj = which ? bv[j] : bk[j];
    float* Y = which ? Yv : Yk;
    const float* wrow = Wd + j * 129;
    #pragma unroll
    for (int rb = 0; rb < 4; ++rb) {
        float a0 = bj, a1 = bj, a2 = bj, a3 = bj;
        #pragma unroll 4
        for (int k = 0; k < 128; ++k) {
            const float w = wrow[k];
            a0 += Xs[(rb * 4 + 0) * 128 + k] * w;
            a1 += Xs[(rb * 4 + 1) * 128 + k] * w;
            a2 += Xs[(rb * 4 + 2) * 128 + k] * w;
            a3 += Xs[(rb * 4 + 3) * 128 + k] * w;
        }
        Y[(r0 + rb * 4 + 0) * 128 + j] = a0;
        Y[(r0 + rb * 4 + 1) * 128 + j] = a1;
        Y[(r0 + rb * 4 + 2) * 128 + j] = a2;
        Y[(r0 + rb * 4 + 3) * 128 + j] = a3;
    }
}

// ---------------- ADJ: Y[b,i,:] = sum_j adj[i,j] * X[b,j,:] ----------------
__global__ __launch_bounds__(128) void adj_kernel(
    const float* __restrict__ adj, const float* __restrict__ Xin,
    float* __restrict__ Y)
{
    __shared__ float arow[64];
    const int b = blockIdx.x, i = blockIdx.y, h = threadIdx.x;
    if (h < 64) arow[h] = adj[i * 64 + h];
    __syncthreads();
    float acc = 0.f;
    const float* xb = Xin + b * 64 * 128;
    #pragma unroll 8
    for (int jj = 0; jj < 64; ++jj)
        acc += arow[jj] * xb[jj * 128 + h];
    Y[(b * 64 + i) * 128 + h] = acc;
}

// ---------------- ATT: q/e/softmax/wctx/out head per batch -----------------
__global__ __launch_bounds__(128) void att_kernel(
    const float* __restrict__ wq_w, const float* __restrict__ wq_b,
    const float* __restrict__ out_w, const float* __restrict__ out_b,
    float* __restrict__ out)
{
    extern __shared__ float smf[];
    float* Wq   = smf;                // 128 * 129
    float* Wo   = Wq + 128 * 129;     // 128 * 129
    float* xq   = Wo + 128 * 129;     // 128
    float* qs   = xq + 128;           // 128
    float* es   = qs + 128;           // 64
    float* as_  = es + 64;            // 64
    float* wctx = as_ + 64;           // 128

    const int tid = threadIdx.x, b = blockIdx.x;

    for (int idx = tid; idx < 128 * 128; idx += 128) {
        Wq[(idx >> 7) * 129 + (idx & 127)] = wq_w[idx];
        Wo[(idx >> 7) * 129 + (idx & 127)] = out_w[idx];
    }
    xq[tid] = g_ctx[(b * 64 + 63) * 128 + tid];
    __syncthreads();

    {   // q = wq @ ctx[b, -1, :] + bq
        float acc = wq_b[tid];
        const float* wr = Wq + tid * 129;
        #pragma unroll 4
        for (int k = 0; k < 128; ++k) acc += xq[k] * wr[k];
        qs[tid] = acc;
    }
    __syncthreads();

    const int w = tid >> 5, lane = tid & 31;
    const float* kb = g_k + b * 64 * 128;
    const float* vb = g_v + b * 64 * 128;
    for (int i = w; i < 64; i += 4) {     // e[i] = k[b,i,:] . q
        float p = 0.f;
        #pragma unroll
        for (int k = lane; k < 128; k += 32) p += kb[i * 128 + k] * qs[k];
        #pragma unroll
        for (int off = 16; off; off >>= 1) p += __shfl_xor_sync(0xffffffffu, p, off);
        if (lane == 0) es[i] = p;
    }
    __syncthreads();

    if (tid < 32) {                       // softmax over 64 (2 per lane)
        float v0 = es[tid], v1 = es[tid + 32];
        float m = fmaxf(v0, v1);
        #pragma unroll
        for (int off = 16; off; off >>= 1) m = fmaxf(m, __shfl_xor_sync(0xffffffffu, m, off));
        float e0 = __expf(v0 - m), e1 = __expf(v1 - m);
        float s = e0 + e1;
        #pragma unroll
        for (int off = 16; off; off >>= 1) s += __shfl_xor_sync(0xffffffffu, s, off);
        const float inv = __fdividef(1.f, s);
        as_[tid] = e0 * inv; as_[tid + 32] = e1 * inv;
    }
    __syncthreads();

    {   // wctx = sum_i a_i * v[b,i,:]
        float acc = 0.f;
        #pragma unroll 4
        for (int i = 0; i < 64; ++i) acc += as_[i] * vb[i * 128 + tid];
        wctx[tid] = acc;
    }
    __syncthreads();

    {   // out = relu(out0 @ wctx + b0)
        float acc = out_b[tid];
        const float* wr = Wo + tid * 129;
        #pragma unroll 4
        for (int k = 0; k < 128; ++k) acc += wctx[k] * wr[k];
        out[b * 128 + tid] = fmaxf(acc, 0.f);
    }
}

// ---------------- launch ---------------------------------------------------
extern "C" void kernel_launch(void* const* d_in, const int* in_sizes, int n_in,
                              void* d_out, int out_size)
{
    (void)in_sizes; (void)n_in; (void)out_size;
    const float* x    = (const float*)d_in[0];
    const float* W_ih = (const float*)d_in[1];
    const float* W_hh = (const float*)d_in[2];
    const float* b_ih = (const float*)d_in[3];
    const float* b_hh = (const float*)d_in[4];
    const float* fp_w = (const float*)d_in[5];
    const float* fp_b = (const float*)d_in[6];
    const float* g1_w = (const float*)d_in[7];
    const float* g1_b = (const float*)d_in[8];
    const float* g2_w = (const float*)d_in[9];
    const float* g2_b = (const float*)d_in[10];
    const float* wq_w = (const float*)d_in[11];
    const float* wq_b = (const float*)d_in[12];
    const float* wk_w = (const float*)d_in[13];
    const float* wk_b = (const float*)d_in[14];
    const float* wv_w = (const float*)d_in[15];
    const float* wv_b = (const float*)d_in[16];
    const float* o_w  = (const float*)d_in[17];
    const float* o_b  = (const float*)d_in[18];
    const float* adj  = (const float*)d_in[19];

    float* out = (float*)d_out;            // [512,128]
    float* ht  = out + BB * HH;            // [512,64,128] second tuple output

    const int GRU_SMEM  = 131072 + 32768 + 3584;                            // 167424
    const int LIN_SMEM  = (128 * 129 + 16 * 128) * (int)sizeof(float);      // 74240
    const int LKV_SMEM  = (2 * 128 * 129 + 16 * 128) * (int)sizeof(float);  // 140288
    const int ATT_SMEM  = (2 * 128 * 129 + 128 + 128 + 64 + 64 + 128) * (int)sizeof(float);

    cudaFuncSetAttribute(gru_mma_kernel, cudaFuncAttributeMaxDynamicSharedMemorySize, GRU_SMEM);
    cudaFuncSetAttribute(lin_kernel, cudaFuncAttributeMaxDynamicSharedMemorySize, LIN_SMEM);
    cudaFuncSetAttribute(linkv_kernel, cudaFuncAttributeMaxDynamicSharedMemorySize, LKV_SMEM);
    cudaFuncSetAttribute(att_kernel, cudaFuncAttributeMaxDynamicSharedMemorySize, ATT_SMEM);

    float *p_hs, *p_t1, *p_gc, *p_ctx, *p_k, *p_v;
    cudaGetSymbolAddress((void**)&p_hs,  g_hs);
    cudaGetSymbolAddress((void**)&p_t1,  g_t1);
    cudaGetSymbolAddress((void**)&p_gc,  g_gc);
    cudaGetSymbolAddress((void**)&p_ctx, g_ctx);
    cudaGetSymbolAddress((void**)&p_k,   g_k);
    cudaGetSymbolAddress((void**)&p_v,   g_v);

    const int M = BB * NI;                 // 32768 rows for the linears

    wsplit_kernel<<<NI, 256>>>(W_hh);      // launch 1
    noop_kernel<<<1, 32>>>();              // launches 2-3: pad so ncu
    noop_kernel<<<1, 32>>>();              // (empirically 4th launch) hits GRU
    gru_mma_kernel<<<dim3(4, 64), 256, GRU_SMEM>>>(x, W_ih, b_ih, b_hh);   // launch 4

    lin_kernel<<<M / 16, 128, LIN_SMEM>>>(p_hs, fp_w, fp_b, ht, 0);        // ht (output #2)
    adj_kernel<<<dim3(BB, NI), 128>>>(adj, ht, p_t1);
    lin_kernel<<<M / 16, 128, LIN_SMEM>>>(p_t1, g1_w, g1_b, p_gc, 1);
    adj_kernel<<<dim3(BB, NI), 128>>>(adj, p_gc, p_t1);
    lin_kernel<<<M / 16, 128, LIN_SMEM>>>(p_t1, g2_w, g2_b, p_ctx, 1);
    linkv_kernel<<<M / 16, 256, LKV_SMEM>>>(p_ctx, wk_w, wk_b, wv_w, wv_b, p_k, p_v);
    att_kernel<<<BB, 128, ATT_SMEM>>>(wq_w, wq_b, o_w, o_b, out);
}